// round 3
// baseline (speedup 1.0000x reference)
#include <cuda_runtime.h>
#include <math.h>

// Problem constants
#define BB 16
#define DD 512
#define HWX 1024          // H*W
#define NN 16384          // B*H*W
#define MM 2000

// Output layout (float32, concatenated in reference return order)
#define UQ_OFF 0LL                 // updated_query  (16,1024,32,32) = 16777216
#define UM_OFF 16777216LL          // updated_memory (2000,512)       = 1024000
#define SQ_OFF 17801216LL          // score_query    (16384,2000)     = 32768000
#define SMO_OFF 50569216LL         // score_memory   (16384,2000)     = 32768000
#define LS_OFF 83337216LL          // separateness, compactness

// Per-batch stride of updated_query: 2*D * H*W = 1024*1024
#define UQ_BSTRIDE 1048576LL

// ---------------- scratch (device globals; no allocation allowed) ----------
__device__ float g_qf[NN * DD];        // normalized+transposed query (N,512)
__device__ float g_kn[MM * DD];        // normalized keys
__device__ float g_norm2[NN];
__device__ int   g_top1[NN];
__device__ float g_E1[NN];             // exp(10*top1 score), bitwise same as SQ buffer entry
__device__ float g_colsum[MM];
__device__ float g_colmaxE[MM];
__device__ float g_colinv[MM];
__device__ float g_wraw[NN];
__device__ float g_denom[MM];
__device__ float g_qupd[MM * DD];
__device__ float g_loss[2];            // [0]=separateness sum, [1]=compactness sum

// ---------------- helpers --------------------------------------------------
__device__ __forceinline__ bool gt2(float va, int ia, float vb, int ib) {
    return va > vb || (va == vb && (unsigned)ia < (unsigned)ib);
}

__device__ __forceinline__ float block_reduce_sum256(float v, float* red) {
    int tid = threadIdx.x;
    red[tid] = v; __syncthreads();
    #pragma unroll
    for (int s = 128; s > 0; s >>= 1) {
        if (tid < s) red[tid] += red[tid + s];
        __syncthreads();
    }
    float r = red[0];
    __syncthreads();
    return r;
}

// ---------------- K0: zero scratch ----------------------------------------
__global__ void k_zero() {
    int i = blockIdx.x * 256 + threadIdx.x;       // grid covers MM*DD = 1,024,000
    if (i < MM * DD) g_qupd[i] = 0.f;
    if (i < MM) { g_denom[i] = 0.f; g_colsum[i] = 0.f; g_colmaxE[i] = 0.f; }
    if (i < NN) g_norm2[i] = 0.f;
    if (i < 2)  g_loss[i] = 0.f;
}

// ---------------- K1a: per-pixel query norm^2 (coalesced) ------------------
__global__ void k_qnorm(const float* __restrict__ q) {
    int n = blockIdx.x * 256 + threadIdx.x;       // grid (64, 4)
    int b = n >> 10, hw = n & 1023;
    const float* p = q + (size_t)b * 524288 + (size_t)blockIdx.y * 131072 + hw;
    float s = 0.f;
    #pragma unroll 4
    for (int d = 0; d < 128; d++) { float v = p[(size_t)d * 1024]; s += v * v; }
    atomicAdd(&g_norm2[n], s);
}

// ---------------- K1b: write qf (transposed) + updated_query first half ----
__global__ void k_writeqf(const float* __restrict__ q, float* __restrict__ outb) {
    // grid (16 dtile, 32 hwtile, 16 b), block (32, 8)
    int b = blockIdx.z, d0 = blockIdx.x * 32, hw0 = blockIdx.y * 32;
    int tx = threadIdx.x, ty = threadIdx.y;
    __shared__ float tile[32][33];
    __shared__ float inv_s[32];
    if (ty == 0) {
        float nr = sqrtf(g_norm2[b * 1024 + hw0 + tx]);
        inv_s[tx] = 1.0f / fmaxf(nr, 1e-12f);
    }
    __syncthreads();
    const float* qb = q + (size_t)b * 524288;
    float* uq = outb + (size_t)b * UQ_BSTRIDE;    // 1024 channels * 1024 HW per batch
    #pragma unroll
    for (int qq = 0; qq < 4; qq++) {
        int d = d0 + ty + qq * 8;
        float v = qb[(size_t)d * 1024 + hw0 + tx] * inv_s[tx];
        tile[ty + qq * 8][tx] = v;
        uq[(size_t)d * 1024 + hw0 + tx] = v;      // first half of updated_query
    }
    __syncthreads();
    #pragma unroll
    for (int qq = 0; qq < 4; qq++) {
        int r = ty + qq * 8;
        g_qf[(size_t)(b * 1024 + hw0 + r) * 512 + d0 + tx] = tile[tx][r];
    }
}

// ---------------- K2: normalize keys ---------------------------------------
__global__ void k_keynorm(const float* __restrict__ keys) {
    int m = blockIdx.x, tid = threadIdx.x;        // 2000 blocks x 256
    __shared__ float red[256];
    const float* kp = keys + (size_t)m * 512;
    float v0 = kp[tid], v1 = kp[tid + 256];
    float s = block_reduce_sum256(v0 * v0 + v1 * v1, red);
    float inv = 1.0f / fmaxf(sqrtf(s), 1e-12f);
    g_kn[(size_t)m * 512 + tid]       = v0 * inv;
    g_kn[(size_t)m * 512 + tid + 256] = v1 * inv;
}

// ---------------- K3: score GEMM  S = qf (Nx512) * kn^T (Mx512) ------------
__global__ __launch_bounds__(256) void k_gemm_score(float* __restrict__ outb) {
    float* C = outb + SMO_OFF;                    // raw scores into SM region
    int i0 = blockIdx.x * 64;                     // N tile
    int j0 = blockIdx.y * 64;                     // M tile
    __shared__ float As[16][68];
    __shared__ float Bs[16][68];
    int t = threadIdx.x;
    int tx = t & 15, ty = t >> 4;
    int lr = t >> 2, lc = (t & 3) << 2;
    float acc[4][4] = {};
    const float* Ap = g_qf + (size_t)(i0 + lr) * 512 + lc;
    bool bvalid = (j0 + lr) < MM;
    int brow = bvalid ? (j0 + lr) : (MM - 1);
    const float* Bp = g_kn + (size_t)brow * 512 + lc;
    for (int k0 = 0; k0 < 512; k0 += 16) {
        float4 av = *(const float4*)(Ap + k0);
        float4 bv = bvalid ? *(const float4*)(Bp + k0) : make_float4(0.f,0.f,0.f,0.f);
        As[lc+0][lr]=av.x; As[lc+1][lr]=av.y; As[lc+2][lr]=av.z; As[lc+3][lr]=av.w;
        Bs[lc+0][lr]=bv.x; Bs[lc+1][lr]=bv.y; Bs[lc+2][lr]=bv.z; Bs[lc+3][lr]=bv.w;
        __syncthreads();
        #pragma unroll
        for (int k = 0; k < 16; k++) {
            float4 a = *(const float4*)&As[k][ty << 2];
            float4 b = *(const float4*)&Bs[k][tx << 2];
            float aa[4] = {a.x,a.y,a.z,a.w}, bb[4] = {b.x,b.y,b.z,b.w};
            #pragma unroll
            for (int ii = 0; ii < 4; ii++)
                #pragma unroll
                for (int jj = 0; jj < 4; jj++) acc[ii][jj] += aa[ii] * bb[jj];
        }
        __syncthreads();
    }
    #pragma unroll
    for (int ii = 0; ii < 4; ii++) {
        int i = i0 + (ty << 2) + ii;
        int j = j0 + (tx << 2);
        float* Cp = C + (size_t)i * MM + j;
        if (j + 3 < MM) *(float4*)Cp = make_float4(acc[ii][0], acc[ii][1], acc[ii][2], acc[ii][3]);
        else { for (int jj = 0; jj < 4; jj++) if (j + jj < MM) Cp[jj] = acc[ii][jj]; }
    }
}

// ---------------- K5: per-row pass -----------------------------------------
// Reads raw scores, finds top2, writes E=exp(10*s) to SQ region (unnormalized)
// and row softmax to SM region; accumulates both losses.
__global__ __launch_bounds__(256) void k_rows(float* __restrict__ outb,
                                              const float* __restrict__ keys) {
    int n = blockIdx.x, tid = threadIdx.x;
    float* Sr = outb + SMO_OFF + (size_t)n * MM;
    float* Qr = outb + SQ_OFF + (size_t)n * MM;
    __shared__ float row[2048];
    __shared__ float rv1[256], rv2[256];
    __shared__ int   ri1[256], ri2[256];
    __shared__ float red[256];

    for (int m = tid; m < MM; m += 256) row[m] = Sr[m];
    __syncthreads();

    // local top2
    float v1 = -3.0e38f, v2 = -3.0e38f; int i1 = 0x7FFFFFFF, i2 = 0x7FFFFFFF;
    for (int m = tid; m < MM; m += 256) {
        float v = row[m];
        if (gt2(v, m, v1, i1)) { v2 = v1; i2 = i1; v1 = v; i1 = m; }
        else if (gt2(v, m, v2, i2)) { v2 = v; i2 = m; }
    }
    rv1[tid] = v1; ri1[tid] = i1; rv2[tid] = v2; ri2[tid] = i2;
    __syncthreads();
    for (int s = 128; s > 0; s >>= 1) {
        if (tid < s) {
            float a1 = rv1[tid], a2 = rv2[tid]; int b1 = ri1[tid], b2 = ri2[tid];
            float w1 = rv1[tid + s], w2 = rv2[tid + s]; int j1 = ri1[tid + s], j2 = ri2[tid + s];
            float o1, o2; int p1, p2;
            if (gt2(a1, b1, w1, j1)) {
                o1 = a1; p1 = b1;
                if (gt2(w1, j1, a2, b2)) { o2 = w1; p2 = j1; } else { o2 = a2; p2 = b2; }
            } else {
                o1 = w1; p1 = j1;
                if (gt2(a1, b1, w2, j2)) { o2 = a1; p2 = b1; } else { o2 = w2; p2 = j2; }
            }
            rv1[tid] = o1; ri1[tid] = p1; rv2[tid] = o2; ri2[tid] = p2;
        }
        __syncthreads();
    }
    int gg1 = ri1[0], gg2 = ri2[0];

    // E = exp(10*s) (bounded: |s|<=1). Write unnormalized E to SQ region.
    float zs = 0.f;
    for (int m = tid; m < MM; m += 256) {
        float e = __expf(row[m] * 10.0f);
        row[m] = e; Qr[m] = e; zs += e;
    }
    zs = block_reduce_sum256(zs, red);
    float invZ = 1.0f / zs;
    for (int m = tid; m < MM; m += 256) Sr[m] = row[m] * invZ;   // score_memory

    // losses using raw keys
    float c2 = 0.f, p2s = 0.f, n2s = 0.f;
    const float* qrow = g_qf + (size_t)n * 512;
    const float* k1 = keys + (size_t)gg1 * 512;
    const float* k2 = keys + (size_t)gg2 * 512;
    for (int d = tid; d < 512; d += 256) {
        float qv = qrow[d];
        float df = qv - k1[d];           c2 += df * df;
        float dp = df + 1e-6f;           p2s += dp * dp;
        float dn = (qv - k2[d]) + 1e-6f; n2s += dn * dn;
    }
    c2  = block_reduce_sum256(c2,  red);
    p2s = block_reduce_sum256(p2s, red);
    n2s = block_reduce_sum256(n2s, red);
    if (tid == 0) {
        atomicAdd(&g_loss[0], fmaxf(sqrtf(p2s) - sqrtf(n2s) + 1.0f, 0.0f));
        atomicAdd(&g_loss[1], c2);
        g_top1[n] = gg1;
        g_E1[n] = row[gg1];              // identical bits to value in SQ buffer
    }
}

// ---------------- K6a: column sum + max of E --------------------------------
__global__ void k_colreduce(const float* __restrict__ outb) {
    const float* E = outb + SQ_OFF;
    int tx = threadIdx.x & 31, ty = threadIdx.x >> 5;   // grid (63, 8)
    int m = blockIdx.x * 32 + tx;
    int n0 = blockIdx.y * 2048;
    float s = 0.f, mx = 0.f;
    if (m < MM) {
        const float* p = E + (size_t)n0 * MM + m;
        for (int r = ty; r < 2048; r += 8) { float v = p[(size_t)r * MM]; s += v; mx = fmaxf(mx, v); }
    }
    __shared__ float ss[8][33], sx[8][33];
    ss[ty][tx] = s; sx[ty][tx] = mx; __syncthreads();
    if (ty == 0 && m < MM) {
        for (int r = 1; r < 8; r++) { s += ss[r][tx]; mx = fmaxf(mx, sx[r][tx]); }
        atomicAdd(&g_colsum[m], s);
        atomicMax((int*)&g_colmaxE[m], __float_as_int(mx));  // E > 0, int order ok
    }
}

__global__ void k_colinv() {
    int m = blockIdx.x * 256 + threadIdx.x;
    if (m < MM) g_colinv[m] = 1.0f / g_colsum[m];
}

// ---------------- K6c: scale SQ in place -----------------------------------
__global__ void k_scale_sq(float* __restrict__ outb) {
    float* Qr = outb + SQ_OFF + (size_t)blockIdx.x * MM;
    for (int m = threadIdx.x; m < MM; m += 256) Qr[m] *= g_colinv[m];
}

// ---------------- K7a: w_raw + denom ---------------------------------------
__global__ void k_wraw() {
    int n = blockIdx.x * 256 + threadIdx.x;       // 64 blocks
    int g = g_top1[n];
    float ci = g_colinv[g];
    float sq = g_E1[n] * ci;                      // == SQ[n, g] after scaling
    float cm = g_colmaxE[g] * ci;                 // == max of SQ column g
    float wr = sq / (cm + 1e-8f);
    g_wraw[n] = wr;
    atomicAdd(&g_denom[g], wr);
}

// ---------------- K7b: weighted segment scatter -----------------------------
__global__ void k_scatter() {
    int n = blockIdx.x;
    int g = g_top1[n];
    float w = g_wraw[n] / (g_denom[g] + 1e-8f);
    const float* qrow = g_qf + (size_t)n * 512;
    float* dst = g_qupd + (size_t)g * 512;
    for (int d = threadIdx.x; d < 512; d += 256) atomicAdd(&dst[d], w * qrow[d]);
}

// ---------------- K8: updated_memory ---------------------------------------
__global__ void k_umem(float* __restrict__ outb, const float* __restrict__ keys) {
    int m = blockIdx.x, tid = threadIdx.x;        // 2000 blocks x 256
    __shared__ float red[256];
    float a0 = g_qupd[(size_t)m * 512 + tid]       + keys[(size_t)m * 512 + tid];
    float a1 = g_qupd[(size_t)m * 512 + tid + 256] + keys[(size_t)m * 512 + tid + 256];
    float s = block_reduce_sum256(a0 * a0 + a1 * a1, red);
    float inv = 1.0f / fmaxf(sqrtf(s), 1e-12f);
    float* um = outb + UM_OFF + (size_t)m * 512;
    um[tid] = a0 * inv; um[tid + 256] = a1 * inv;
}

// ---------------- K9: finalize losses --------------------------------------
__global__ void k_final(float* __restrict__ outb) {
    outb[LS_OFF]     = g_loss[0] * (1.0f / 16384.0f);
    outb[LS_OFF + 1] = g_loss[1] * (1.0f / 8388608.0f);
}

// ---------------- K6g: concat GEMM  CM = SM (Nx2000) * keys (2000x512) ------
// Writes directly into updated_query second half with (b, 512+j, hw) layout.
__global__ __launch_bounds__(256) void k_gemm_concat(float* __restrict__ outb,
                                                     const float* __restrict__ keys) {
    const float* A = outb + SMO_OFF;              // row softmax (N x 2000)
    int i0 = blockIdx.x * 64;                     // N tile (256 blocks)
    int j0 = blockIdx.y * 64;                     // D tile (8 blocks)
    __shared__ float As[16][68];
    __shared__ float Bs[16][68];
    int t = threadIdx.x;
    int tx = t & 15, ty = t >> 4;
    int lr = t >> 2, lc = (t & 3) << 2;           // A loader
    int kr = t >> 4, jc = (t & 15) << 2;          // B loader
    float acc[4][4] = {};
    for (int k0 = 0; k0 < 2000; k0 += 16) {
        float4 av = *(const float4*)(A + (size_t)(i0 + lr) * MM + k0 + lc);
        float4 bv = *(const float4*)(keys + (size_t)(k0 + kr) * 512 + j0 + jc);
        As[lc+0][lr]=av.x; As[lc+1][lr]=av.y; As[lc+2][lr]=av.z; As[lc+3][lr]=av.w;
        *(float4*)&Bs[kr][jc] = bv;
        __syncthreads();
        #pragma unroll
        for (int k = 0; k < 16; k++) {
            float4 a = *(const float4*)&As[k][ty << 2];
            float4 b = *(const float4*)&Bs[k][tx << 2];
            float aa[4] = {a.x,a.y,a.z,a.w}, bb[4] = {b.x,b.y,b.z,b.w};
            #pragma unroll
            for (int ii = 0; ii < 4; ii++)
                #pragma unroll
                for (int jj = 0; jj < 4; jj++) acc[ii][jj] += aa[ii] * bb[jj];
        }
        __syncthreads();
    }
    int i = i0 + (ty << 2);
    int bq = i >> 10, hw = i & 1023;
    // updated_query second half: out[bq][512 + j][hw], 1024 channels per batch
    float* base = outb + ((size_t)bq * 1024 + 512) * 1024 + hw;
    #pragma unroll
    for (int jj = 0; jj < 4; jj++) {
        int j = j0 + (tx << 2) + jj;
        *(float4*)&base[(size_t)j * 1024] =
            make_float4(acc[0][jj], acc[1][jj], acc[2][jj], acc[3][jj]);
    }
}

// ---------------- launch ----------------------------------------------------
extern "C" void kernel_launch(void* const* d_in, const int* in_sizes, int n_in,
                              void* d_out, int out_size) {
    const float* q    = (const float*)d_in[0];   // (16,512,32,32)
    const float* keys = (const float*)d_in[1];   // (2000,512)
    float* out = (float*)d_out;

    k_zero<<<4000, 256>>>();
    k_qnorm<<<dim3(64, 4), 256>>>(q);
    k_writeqf<<<dim3(16, 32, 16), dim3(32, 8)>>>(q, out);
    k_keynorm<<<2000, 256>>>(keys);
    k_gemm_score<<<dim3(256, 32), 256>>>(out);
    k_rows<<<16384, 256>>>(out, keys);
    k_colreduce<<<dim3(63, 8), 256>>>(out);
    k_colinv<<<8, 256>>>();
    k_scale_sq<<<16384, 256>>>(out);
    k_wraw<<<64, 256>>>();
    k_gemm_concat<<<dim3(256, 8), 256>>>(out, keys);
    k_scatter<<<16384, 256>>>();
    k_umem<<<2000, 256>>>(out, keys);
    k_final<<<1, 1>>>(out);
}

// round 4
// speedup vs baseline: 1.5777x; 1.5777x over previous
#include <cuda_runtime.h>
#include <math.h>

// Problem constants
#define BB 16
#define DD 512
#define HWX 1024          // H*W
#define NN 16384          // B*H*W
#define MM 2000

// Output layout (float32, concatenated in reference return order)
#define UQ_OFF 0LL                 // updated_query  (16,1024,32,32) = 16777216
#define UM_OFF 16777216LL          // updated_memory (2000,512)       = 1024000
#define SQ_OFF 17801216LL          // score_query    (16384,2000)     = 32768000
#define SMO_OFF 50569216LL         // score_memory   (16384,2000)     = 32768000
#define LS_OFF 83337216LL          // separateness, compactness

// Per-batch stride of updated_query: 2*D * H*W = 1024*1024
#define UQ_BSTRIDE 1048576LL

// ---------------- scratch (device globals; no allocation allowed) ----------
__device__ float g_qf[NN * DD];        // normalized+transposed query (N,512)
__device__ float g_kn[MM * DD];        // normalized keys
__device__ float g_norm2[NN];
__device__ int   g_top1[NN];
__device__ float g_E1[NN];             // exp(10*top1 score), bitwise same as SQ buffer entry
__device__ float g_colsum[MM];
__device__ float g_colmaxE[MM];
__device__ float g_colinv[MM];
__device__ float g_wraw[NN];
__device__ float g_denom[MM];
__device__ float g_qupd[MM * DD];
__device__ float g_loss[2];            // [0]=separateness sum, [1]=compactness sum

// ---------------- helpers --------------------------------------------------
__device__ __forceinline__ bool gt2(float va, int ia, float vb, int ib) {
    return va > vb || (va == vb && (unsigned)ia < (unsigned)ib);
}

__device__ __forceinline__ float block_reduce_sum256(float v, float* red) {
    int tid = threadIdx.x;
    red[tid] = v; __syncthreads();
    #pragma unroll
    for (int s = 128; s > 0; s >>= 1) {
        if (tid < s) red[tid] += red[tid + s];
        __syncthreads();
    }
    float r = red[0];
    __syncthreads();
    return r;
}

// ---------------- K0: zero scratch ----------------------------------------
__global__ void k_zero() {
    int i = blockIdx.x * 256 + threadIdx.x;       // grid covers MM*DD = 1,024,000
    if (i < MM * DD) g_qupd[i] = 0.f;
    if (i < MM) { g_denom[i] = 0.f; g_colsum[i] = 0.f; g_colmaxE[i] = 0.f; }
    if (i < NN) g_norm2[i] = 0.f;
    if (i < 2)  g_loss[i] = 0.f;
}

// ---------------- K1a: per-pixel query norm^2 (coalesced) ------------------
__global__ void k_qnorm(const float* __restrict__ q) {
    int n = blockIdx.x * 256 + threadIdx.x;       // grid (64, 4)
    int b = n >> 10, hw = n & 1023;
    const float* p = q + (size_t)b * 524288 + (size_t)blockIdx.y * 131072 + hw;
    float s = 0.f;
    #pragma unroll 4
    for (int d = 0; d < 128; d++) { float v = p[(size_t)d * 1024]; s += v * v; }
    atomicAdd(&g_norm2[n], s);
}

// ---------------- K1b: write qf (transposed) + updated_query first half ----
__global__ void k_writeqf(const float* __restrict__ q, float* __restrict__ outb) {
    // grid (16 dtile, 32 hwtile, 16 b), block (32, 8)
    int b = blockIdx.z, d0 = blockIdx.x * 32, hw0 = blockIdx.y * 32;
    int tx = threadIdx.x, ty = threadIdx.y;
    __shared__ float tile[32][33];
    __shared__ float inv_s[32];
    if (ty == 0) {
        float nr = sqrtf(g_norm2[b * 1024 + hw0 + tx]);
        inv_s[tx] = 1.0f / fmaxf(nr, 1e-12f);
    }
    __syncthreads();
    const float* qb = q + (size_t)b * 524288;
    float* uq = outb + (size_t)b * UQ_BSTRIDE;    // 1024 channels * 1024 HW per batch
    #pragma unroll
    for (int qq = 0; qq < 4; qq++) {
        int d = d0 + ty + qq * 8;
        float v = qb[(size_t)d * 1024 + hw0 + tx] * inv_s[tx];
        tile[ty + qq * 8][tx] = v;
        uq[(size_t)d * 1024 + hw0 + tx] = v;      // first half of updated_query
    }
    __syncthreads();
    #pragma unroll
    for (int qq = 0; qq < 4; qq++) {
        int r = ty + qq * 8;
        g_qf[(size_t)(b * 1024 + hw0 + r) * 512 + d0 + tx] = tile[tx][r];
    }
}

// ---------------- K2: normalize keys ---------------------------------------
__global__ void k_keynorm(const float* __restrict__ keys) {
    int m = blockIdx.x, tid = threadIdx.x;        // 2000 blocks x 256
    __shared__ float red[256];
    const float* kp = keys + (size_t)m * 512;
    float v0 = kp[tid], v1 = kp[tid + 256];
    float s = block_reduce_sum256(v0 * v0 + v1 * v1, red);
    float inv = 1.0f / fmaxf(sqrtf(s), 1e-12f);
    g_kn[(size_t)m * 512 + tid]       = v0 * inv;
    g_kn[(size_t)m * 512 + tid + 256] = v1 * inv;
}

// ---------------- K3: score GEMM  S = qf (Nx512) * kn^T (Mx512) ------------
__global__ __launch_bounds__(256) void k_gemm_score(float* __restrict__ outb) {
    float* C = outb + SMO_OFF;                    // raw scores into SM region
    int i0 = blockIdx.x * 64;                     // N tile
    int j0 = blockIdx.y * 64;                     // M tile
    __shared__ float As[16][68];
    __shared__ float Bs[16][68];
    int t = threadIdx.x;
    int tx = t & 15, ty = t >> 4;
    int lr = t >> 2, lc = (t & 3) << 2;
    float acc[4][4] = {};
    const float* Ap = g_qf + (size_t)(i0 + lr) * 512 + lc;
    bool bvalid = (j0 + lr) < MM;
    int brow = bvalid ? (j0 + lr) : (MM - 1);
    const float* Bp = g_kn + (size_t)brow * 512 + lc;
    for (int k0 = 0; k0 < 512; k0 += 16) {
        float4 av = *(const float4*)(Ap + k0);
        float4 bv = bvalid ? *(const float4*)(Bp + k0) : make_float4(0.f,0.f,0.f,0.f);
        As[lc+0][lr]=av.x; As[lc+1][lr]=av.y; As[lc+2][lr]=av.z; As[lc+3][lr]=av.w;
        Bs[lc+0][lr]=bv.x; Bs[lc+1][lr]=bv.y; Bs[lc+2][lr]=bv.z; Bs[lc+3][lr]=bv.w;
        __syncthreads();
        #pragma unroll
        for (int k = 0; k < 16; k++) {
            float4 a = *(const float4*)&As[k][ty << 2];
            float4 b = *(const float4*)&Bs[k][tx << 2];
            float aa[4] = {a.x,a.y,a.z,a.w}, bb[4] = {b.x,b.y,b.z,b.w};
            #pragma unroll
            for (int ii = 0; ii < 4; ii++)
                #pragma unroll
                for (int jj = 0; jj < 4; jj++) acc[ii][jj] += aa[ii] * bb[jj];
        }
        __syncthreads();
    }
    #pragma unroll
    for (int ii = 0; ii < 4; ii++) {
        int i = i0 + (ty << 2) + ii;
        int j = j0 + (tx << 2);
        float* Cp = C + (size_t)i * MM + j;
        if (j + 3 < MM) *(float4*)Cp = make_float4(acc[ii][0], acc[ii][1], acc[ii][2], acc[ii][3]);
        else { for (int jj = 0; jj < 4; jj++) if (j + jj < MM) Cp[jj] = acc[ii][jj]; }
    }
}

// ---------------- K5: per-row pass -----------------------------------------
// Reads raw scores, finds top2, writes E=exp(10*s) to SQ region (unnormalized)
// and row softmax to SM region; accumulates both losses.
__global__ __launch_bounds__(256) void k_rows(float* __restrict__ outb,
                                              const float* __restrict__ keys) {
    int n = blockIdx.x, tid = threadIdx.x;
    float* Sr = outb + SMO_OFF + (size_t)n * MM;
    float* Qr = outb + SQ_OFF + (size_t)n * MM;
    __shared__ float row[2048];
    __shared__ float rv1[256], rv2[256];
    __shared__ int   ri1[256], ri2[256];
    __shared__ float red[256];

    for (int m = tid; m < MM; m += 256) row[m] = Sr[m];
    __syncthreads();

    // local top2
    float v1 = -3.0e38f, v2 = -3.0e38f; int i1 = 0x7FFFFFFF, i2 = 0x7FFFFFFF;
    for (int m = tid; m < MM; m += 256) {
        float v = row[m];
        if (gt2(v, m, v1, i1)) { v2 = v1; i2 = i1; v1 = v; i1 = m; }
        else if (gt2(v, m, v2, i2)) { v2 = v; i2 = m; }
    }
    rv1[tid] = v1; ri1[tid] = i1; rv2[tid] = v2; ri2[tid] = i2;
    __syncthreads();
    for (int s = 128; s > 0; s >>= 1) {
        if (tid < s) {
            float a1 = rv1[tid], a2 = rv2[tid]; int b1 = ri1[tid], b2 = ri2[tid];
            float w1 = rv1[tid + s], w2 = rv2[tid + s]; int j1 = ri1[tid + s], j2 = ri2[tid + s];
            float o1, o2; int p1, p2;
            if (gt2(a1, b1, w1, j1)) {
                o1 = a1; p1 = b1;
                if (gt2(w1, j1, a2, b2)) { o2 = w1; p2 = j1; } else { o2 = a2; p2 = b2; }
            } else {
                o1 = w1; p1 = j1;
                if (gt2(a1, b1, w2, j2)) { o2 = a1; p2 = b1; } else { o2 = w2; p2 = j2; }
            }
            rv1[tid] = o1; ri1[tid] = p1; rv2[tid] = o2; ri2[tid] = p2;
        }
        __syncthreads();
    }
    int gg1 = ri1[0], gg2 = ri2[0];

    // E = exp(10*s) (bounded: |s|<=1). Write unnormalized E to SQ region.
    float zs = 0.f;
    for (int m = tid; m < MM; m += 256) {
        float e = __expf(row[m] * 10.0f);
        row[m] = e; Qr[m] = e; zs += e;
    }
    zs = block_reduce_sum256(zs, red);
    float invZ = 1.0f / zs;
    for (int m = tid; m < MM; m += 256) Sr[m] = row[m] * invZ;   // score_memory

    // losses using raw keys
    float c2 = 0.f, p2s = 0.f, n2s = 0.f;
    const float* qrow = g_qf + (size_t)n * 512;
    const float* k1 = keys + (size_t)gg1 * 512;
    const float* k2 = keys + (size_t)gg2 * 512;
    for (int d = tid; d < 512; d += 256) {
        float qv = qrow[d];
        float df = qv - k1[d];           c2 += df * df;
        float dp = df + 1e-6f;           p2s += dp * dp;
        float dn = (qv - k2[d]) + 1e-6f; n2s += dn * dn;
    }
    c2  = block_reduce_sum256(c2,  red);
    p2s = block_reduce_sum256(p2s, red);
    n2s = block_reduce_sum256(n2s, red);
    if (tid == 0) {
        atomicAdd(&g_loss[0], fmaxf(sqrtf(p2s) - sqrtf(n2s) + 1.0f, 0.0f));
        atomicAdd(&g_loss[1], c2);
        g_top1[n] = gg1;
        g_E1[n] = row[gg1];              // identical bits to value in SQ buffer
    }
}

// ---------------- K6a: column sum + max of E --------------------------------
__global__ void k_colreduce(const float* __restrict__ outb) {
    const float* E = outb + SQ_OFF;
    int tx = threadIdx.x & 31, ty = threadIdx.x >> 5;   // grid (63, 8)
    int m = blockIdx.x * 32 + tx;
    int n0 = blockIdx.y * 2048;
    float s = 0.f, mx = 0.f;
    if (m < MM) {
        const float* p = E + (size_t)n0 * MM + m;
        for (int r = ty; r < 2048; r += 8) { float v = p[(size_t)r * MM]; s += v; mx = fmaxf(mx, v); }
    }
    __shared__ float ss[8][33], sx[8][33];
    ss[ty][tx] = s; sx[ty][tx] = mx; __syncthreads();
    if (ty == 0 && m < MM) {
        for (int r = 1; r < 8; r++) { s += ss[r][tx]; mx = fmaxf(mx, sx[r][tx]); }
        atomicAdd(&g_colsum[m], s);
        atomicMax((int*)&g_colmaxE[m], __float_as_int(mx));  // E > 0, int order ok
    }
}

__global__ void k_colinv() {
    int m = blockIdx.x * 256 + threadIdx.x;
    if (m < MM) g_colinv[m] = 1.0f / g_colsum[m];
}

// ---------------- K6c: scale SQ in place -----------------------------------
__global__ void k_scale_sq(float* __restrict__ outb) {
    float* Qr = outb + SQ_OFF + (size_t)blockIdx.x * MM;
    for (int m = threadIdx.x; m < MM; m += 256) Qr[m] *= g_colinv[m];
}

// ---------------- K7a: w_raw + denom ---------------------------------------
__global__ void k_wraw() {
    int n = blockIdx.x * 256 + threadIdx.x;       // 64 blocks
    int g = g_top1[n];
    float ci = g_colinv[g];
    float sq = g_E1[n] * ci;                      // == SQ[n, g] after scaling
    float cm = g_colmaxE[g] * ci;                 // == max of SQ column g
    float wr = sq / (cm + 1e-8f);
    g_wraw[n] = wr;
    atomicAdd(&g_denom[g], wr);
}

// ---------------- K7b: weighted segment scatter -----------------------------
__global__ void k_scatter() {
    int n = blockIdx.x;
    int g = g_top1[n];
    float w = g_wraw[n] / (g_denom[g] + 1e-8f);
    const float* qrow = g_qf + (size_t)n * 512;
    float* dst = g_qupd + (size_t)g * 512;
    for (int d = threadIdx.x; d < 512; d += 256) atomicAdd(&dst[d], w * qrow[d]);
}

// ---------------- K8: updated_memory ---------------------------------------
__global__ void k_umem(float* __restrict__ outb, const float* __restrict__ keys) {
    int m = blockIdx.x, tid = threadIdx.x;        // 2000 blocks x 256
    __shared__ float red[256];
    float a0 = g_qupd[(size_t)m * 512 + tid]       + keys[(size_t)m * 512 + tid];
    float a1 = g_qupd[(size_t)m * 512 + tid + 256] + keys[(size_t)m * 512 + tid + 256];
    float s = block_reduce_sum256(a0 * a0 + a1 * a1, red);
    float inv = 1.0f / fmaxf(sqrtf(s), 1e-12f);
    float* um = outb + UM_OFF + (size_t)m * 512;
    um[tid] = a0 * inv; um[tid + 256] = a1 * inv;
}

// ---------------- K9: finalize losses --------------------------------------
__global__ void k_final(float* __restrict__ outb) {
    outb[LS_OFF]     = g_loss[0] * (1.0f / 16384.0f);
    outb[LS_OFF + 1] = g_loss[1] * (1.0f / 8388608.0f);
}

// ---------------- K6g: concat GEMM  CM = SM (Nx2000) * keys (2000x512) ------
// Writes directly into updated_query second half with (b, 512+j, hw) layout.
__global__ __launch_bounds__(256) void k_gemm_concat(float* __restrict__ outb,
                                                     const float* __restrict__ keys) {
    const float* A = outb + SMO_OFF;              // row softmax (N x 2000)
    int i0 = blockIdx.x * 64;                     // N tile (256 blocks)
    int j0 = blockIdx.y * 64;                     // D tile (8 blocks)
    __shared__ float As[16][68];
    __shared__ float Bs[16][68];
    int t = threadIdx.x;
    int tx = t & 15, ty = t >> 4;
    int lr = t >> 2, lc = (t & 3) << 2;           // A loader
    int kr = t >> 4, jc = (t & 15) << 2;          // B loader
    float acc[4][4] = {};
    for (int k0 = 0; k0 < 2000; k0 += 16) {
        float4 av = *(const float4*)(A + (size_t)(i0 + lr) * MM + k0 + lc);
        float4 bv = *(const float4*)(keys + (size_t)(k0 + kr) * 512 + j0 + jc);
        As[lc+0][lr]=av.x; As[lc+1][lr]=av.y; As[lc+2][lr]=av.z; As[lc+3][lr]=av.w;
        *(float4*)&Bs[kr][jc] = bv;
        __syncthreads();
        #pragma unroll
        for (int k = 0; k < 16; k++) {
            float4 a = *(const float4*)&As[k][ty << 2];
            float4 b = *(const float4*)&Bs[k][tx << 2];
            float aa[4] = {a.x,a.y,a.z,a.w}, bb[4] = {b.x,b.y,b.z,b.w};
            #pragma unroll
            for (int ii = 0; ii < 4; ii++)
                #pragma unroll
                for (int jj = 0; jj < 4; jj++) acc[ii][jj] += aa[ii] * bb[jj];
        }
        __syncthreads();
    }
    int i = i0 + (ty << 2);
    int bq = i >> 10, hw = i & 1023;
    // updated_query second half: out[bq][512 + j][hw], 1024 channels per batch
    float* base = outb + ((size_t)bq * 1024 + 512) * 1024 + hw;
    #pragma unroll
    for (int jj = 0; jj < 4; jj++) {
        int j = j0 + (tx << 2) + jj;
        *(float4*)&base[(size_t)j * 1024] =
            make_float4(acc[0][jj], acc[1][jj], acc[2][jj], acc[3][jj]);
    }
}

// ---------------- launch ----------------------------------------------------
extern "C" void kernel_launch(void* const* d_in, const int* in_sizes, int n_in,
                              void* d_out, int out_size) {
    const float* q    = (const float*)d_in[0];   // (16,512,32,32)
    const float* keys = (const float*)d_in[1];   // (2000,512)
    float* out = (float*)d_out;

    k_zero<<<4000, 256>>>();
    k_qnorm<<<dim3(64, 4), 256>>>(q);
    k_writeqf<<<dim3(16, 32, 16), dim3(32, 8)>>>(q, out);
    k_keynorm<<<2000, 256>>>(keys);
    k_gemm_score<<<dim3(256, 32), 256>>>(out);
    k_rows<<<16384, 256>>>(out, keys);
    k_colreduce<<<dim3(63, 8), 256>>>(out);
    k_colinv<<<8, 256>>>();
    k_scale_sq<<<16384, 256>>>(out);
    k_wraw<<<64, 256>>>();
    k_gemm_concat<<<dim3(256, 8), 256>>>(out, keys);
    k_scatter<<<16384, 256>>>();
    k_umem<<<2000, 256>>>(out, keys);
    k_final<<<1, 1>>>(out);
}

// round 7
// speedup vs baseline: 2.2629x; 1.4343x over previous
#include <cuda_runtime.h>
#include <cuda_bf16.h>
#include <math.h>
#include <stdint.h>

#define NN 16384
#define MM 2000
#define MP 2048

#define UQ_OFF 0LL
#define UM_OFF 16777216LL
#define SQ_OFF 17801216LL
#define SMO_OFF 50569216LL
#define LS_OFF 83337216LL
#define UQ_BSTRIDE 1048576LL

// ---------------- scratch ---------------------------------------------------
__device__ float g_qf[(size_t)NN*512];
__device__ __align__(16) __nv_bfloat16 g_qf_h[(size_t)NN*512], g_qf_l[(size_t)NN*512];
__device__ __align__(16) __nv_bfloat16 g_kn_h[(size_t)MP*512], g_kn_l[(size_t)MP*512];
__device__ __align__(16) __nv_bfloat16 g_kT_h[(size_t)512*MP], g_kT_l[(size_t)512*MP];
__device__ __align__(16) __nv_bfloat16 g_sm_h[(size_t)NN*MP],  g_sm_l[(size_t)NN*MP];
__device__ float g_norm2[NN];
__device__ float g_colsum[MM], g_colmaxE[MM], g_colinv[MM];
__device__ float g_wraw[NN];
__device__ int   g_top1[NN];
__device__ float g_denom[MM];
__device__ float g_qupd[(size_t)MM*512];
__device__ float g_loss[2];

// ---------------- helpers ---------------------------------------------------
__device__ __forceinline__ bool gt2(float va, int ia, float vb, int ib) {
    return va > vb || (va == vb && (unsigned)ia < (unsigned)ib);
}
__device__ __forceinline__ float block_reduce_sum256(float v, float* red) {
    int tid = threadIdx.x;
    red[tid] = v; __syncthreads();
    #pragma unroll
    for (int s = 128; s > 0; s >>= 1) { if (tid < s) red[tid] += red[tid + s]; __syncthreads(); }
    float r = red[0]; __syncthreads(); return r;
}
__device__ __forceinline__ void split2(float v, __nv_bfloat16& h, __nv_bfloat16& l) {
    h = __float2bfloat16(v);
    l = __float2bfloat16(v - __bfloat162float(h));
}
__device__ __forceinline__ uint32_t s2u(const void* p) {
    uint32_t a;
    asm("{ .reg .u64 t; cvta.to.shared.u64 t, %1; cvt.u32.u64 %0, t; }" : "=r"(a) : "l"(p));
    return a;
}
__device__ __forceinline__ void ldm_x4(uint32_t* r, uint32_t addr) {
    asm volatile("ldmatrix.sync.aligned.m8n8.x4.shared.b16 {%0,%1,%2,%3}, [%4];"
        : "=r"(r[0]), "=r"(r[1]), "=r"(r[2]), "=r"(r[3]) : "r"(addr));
}
__device__ __forceinline__ void mma16816(float* c, const uint32_t* a, const uint32_t* b) {
    asm volatile("mma.sync.aligned.m16n8k16.row.col.f32.bf16.bf16.f32 "
        "{%0,%1,%2,%3}, {%4,%5,%6,%7}, {%8,%9}, {%0,%1,%2,%3};"
        : "+f"(c[0]), "+f"(c[1]), "+f"(c[2]), "+f"(c[3])
        : "r"(a[0]), "r"(a[1]), "r"(a[2]), "r"(a[3]), "r"(b[0]), "r"(b[1]));
}
#define CPA(dst, src) asm volatile("cp.async.cg.shared.global [%0], [%1], 16;" :: "r"(dst), "l"(src))
#define CPC()  asm volatile("cp.async.commit_group;" ::: "memory")

// ---------------- K0: zero scratch ------------------------------------------
__global__ void k_zero() {
    int i = blockIdx.x * 256 + threadIdx.x;       // 4000*256
    if (i < MM * 512) g_qupd[i] = 0.f;
    if (i < MM) { g_denom[i] = 0.f; g_colsum[i] = 0.f; g_colmaxE[i] = 0.f; }
    if (i < NN) g_norm2[i] = 0.f;
    if (i < 2)  g_loss[i] = 0.f;
    if (i < 48 * 512) {                           // zero padded key rows
        __nv_bfloat16 z = __float2bfloat16(0.f);
        g_kn_h[(size_t)MM * 512 + i] = z;
        g_kn_l[(size_t)MM * 512 + i] = z;
    }
}

// ---------------- K1a: query norm^2 ------------------------------------------
__global__ void k_qnorm(const float* __restrict__ q) {
    int n = blockIdx.x * 256 + threadIdx.x;       // grid (64,4)
    int b = n >> 10, hw = n & 1023;
    const float* p = q + (size_t)b * 524288 + (size_t)blockIdx.y * 131072 + hw;
    float s = 0.f;
    #pragma unroll 4
    for (int d = 0; d < 128; d++) { float v = p[(size_t)d * 1024]; s += v * v; }
    atomicAdd(&g_norm2[n], s);
}

// ---------------- K1b: qf fp32 + bf16 split + UQ first half ------------------
__global__ void k_writeqf(const float* __restrict__ q, float* __restrict__ outb) {
    int b = blockIdx.z, d0 = blockIdx.x * 32, hw0 = blockIdx.y * 32;
    int tx = threadIdx.x, ty = threadIdx.y;
    __shared__ float tile[32][33];
    __shared__ float inv_s[32];
    if (ty == 0) {
        float nr = sqrtf(g_norm2[b * 1024 + hw0 + tx]);
        inv_s[tx] = 1.0f / fmaxf(nr, 1e-12f);
    }
    __syncthreads();
    const float* qb = q + (size_t)b * 524288;
    float* uq = outb + (size_t)b * UQ_BSTRIDE;
    #pragma unroll
    for (int qq = 0; qq < 4; qq++) {
        int d = d0 + ty + qq * 8;
        float v = qb[(size_t)d * 1024 + hw0 + tx] * inv_s[tx];
        tile[ty + qq * 8][tx] = v;
        uq[(size_t)d * 1024 + hw0 + tx] = v;
    }
    __syncthreads();
    #pragma unroll
    for (int qq = 0; qq < 4; qq++) {
        int r = ty + qq * 8;
        float v = tile[tx][r];
        size_t idx = (size_t)(b * 1024 + hw0 + r) * 512 + d0 + tx;
        __nv_bfloat16 h, lo; split2(v, h, lo);
        g_qf[idx] = v; g_qf_h[idx] = h; g_qf_l[idx] = lo;
    }
}

// ---------------- K2: normalized keys bf16 split -----------------------------
__global__ void k_keynorm(const float* __restrict__ keys) {
    int m = blockIdx.x, tid = threadIdx.x;
    __shared__ float red[256];
    const float* kp = keys + (size_t)m * 512;
    float v0 = kp[tid], v1 = kp[tid + 256];
    float s = block_reduce_sum256(v0 * v0 + v1 * v1, red);
    float inv = 1.0f / fmaxf(sqrtf(s), 1e-12f);
    __nv_bfloat16 h, lo;
    split2(v0 * inv, h, lo);
    g_kn_h[(size_t)m * 512 + tid] = h; g_kn_l[(size_t)m * 512 + tid] = lo;
    split2(v1 * inv, h, lo);
    g_kn_h[(size_t)m * 512 + tid + 256] = h; g_kn_l[(size_t)m * 512 + tid + 256] = lo;
}

// ---------------- K2b: raw keys^T (512 x 2048 padded) bf16 split -------------
__global__ void k_keyT(const float* __restrict__ keys) {
    int m0 = blockIdx.x * 32, d0 = blockIdx.y * 32;   // grid (64,16), block (32,8)
    int tx = threadIdx.x, ty = threadIdx.y;
    __shared__ float t[32][33];
    #pragma unroll
    for (int qq = 0; qq < 4; qq++) {
        int ml = ty + qq * 8, m = m0 + ml;
        t[ml][tx] = (m < MM) ? keys[(size_t)m * 512 + d0 + tx] : 0.f;
    }
    __syncthreads();
    #pragma unroll
    for (int qq = 0; qq < 4; qq++) {
        int dl = ty + qq * 8;
        float v = t[tx][dl];
        size_t idx = (size_t)(d0 + dl) * MP + m0 + tx;
        __nv_bfloat16 h, lo; split2(v, h, lo);
        g_kT_h[idx] = h; g_kT_l[idx] = lo;
    }
}

// ---------------- HMMA GEMM (mma.sync bf16, 3-product split) -----------------
// MODE 0: E=exp(10*(qf@kn^T)) -> SQ region   (K=512,  grid 128x16)
// MODE 1: SM@keysT -> updated_query 2nd half (K=2048, grid 128x4)
// Block tile 128x128, BK=32. smem per stage: 4 mats x 128 rows x 80B = 40960B.
#define ROWB 80
#define MATB 10240
#define STG  40960
#define HSM  (2 * STG)

template<int KTOT, int MODE>
__global__ __launch_bounds__(256, 1) void k_mma(float* __restrict__ outb) {
    extern __shared__ char smc[];
    const uint32_t smb = s2u(smc);
    const int tid = threadIdx.x;
    const int lane = tid & 31, wid = tid >> 5;
    const int wr = wid & 3, wc = wid >> 2;
    const int i0 = blockIdx.x * 128, j0 = blockIdx.y * 128;

    const __nv_bfloat16* Ah = (MODE == 0) ? g_qf_h : g_sm_h;
    const __nv_bfloat16* Al = (MODE == 0) ? g_qf_l : g_sm_l;
    const __nv_bfloat16* Bh = (MODE == 0) ? g_kn_h : g_kT_h;
    const __nv_bfloat16* Bl = (MODE == 0) ? g_kn_l : g_kT_l;
    const int lda = (MODE == 0) ? 512 : MP;
    const int ldb = (MODE == 0) ? 512 : MP;

    // loader mapping: 4 matrices x 64 threads; 8 chunks of 16B each
    const int mat = tid >> 6, t6 = tid & 63;
    const __nv_bfloat16* gsrc = (mat == 0) ? Ah : (mat == 1) ? Al : (mat == 2) ? Bh : Bl;
    const int grow0 = (mat < 2) ? i0 : j0;
    const int gld   = (mat < 2) ? lda : ldb;

    float c[2][8][4];
    #pragma unroll
    for (int a = 0; a < 2; a++)
        #pragma unroll
        for (int b = 0; b < 8; b++)
            #pragma unroll
            for (int d = 0; d < 4; d++) c[a][b][d] = 0.f;

    const int NS = KTOT / 32;

    // prologue: stage 0
    {
        uint32_t dst0 = smb + mat * MATB;
        #pragma unroll
        for (int i = 0; i < 8; i++) {
            int chunk = t6 + 64 * i;
            int row = chunk >> 2, kc = chunk & 3;
            CPA(dst0 + row * ROWB + kc * 16, gsrc + (size_t)(grow0 + row) * gld + kc * 8);
        }
        CPC();
    }

    for (int s = 0; s < NS; s++) {
        if (s + 1 < NS) {
            uint32_t dst0 = smb + ((s + 1) & 1) * STG + mat * MATB;
            size_t k0 = (size_t)(s + 1) * 32;
            #pragma unroll
            for (int i = 0; i < 8; i++) {
                int chunk = t6 + 64 * i;
                int row = chunk >> 2, kc = chunk & 3;
                CPA(dst0 + row * ROWB + kc * 16, gsrc + (size_t)(grow0 + row) * gld + k0 + kc * 8);
            }
            CPC();
            asm volatile("cp.async.wait_group 1;" ::: "memory");
        } else {
            asm volatile("cp.async.wait_group 0;" ::: "memory");
        }
        __syncthreads();

        uint32_t sb = smb + (s & 1) * STG;
        #pragma unroll
        for (int kh = 0; kh < 2; kh++) {
            const int k16 = kh * 16;
            uint32_t afh[2][4], afl[2][4], bfh[4][4], bfl[4][4];
            #pragma unroll
            for (int mt = 0; mt < 2; mt++) {
                uint32_t ad = sb + (uint32_t)(wr * 32 + mt * 16 + (lane & 15)) * ROWB
                            + (uint32_t)(k16 + ((lane >> 4) << 3)) * 2;
                ldm_x4(afh[mt], ad);
                ldm_x4(afl[mt], ad + MATB);
            }
            #pragma unroll
            for (int np = 0; np < 4; np++) {
                int n = wc * 64 + np * 16 + ((lane >> 4) << 3) + (lane & 7);
                int kk = k16 + (((lane >> 3) & 1) << 3);
                uint32_t bd = sb + 2 * MATB + (uint32_t)n * ROWB + (uint32_t)kk * 2;
                ldm_x4(bfh[np], bd);
                ldm_x4(bfl[np], bd + MATB);
            }
            #pragma unroll
            for (int mt = 0; mt < 2; mt++)
                #pragma unroll
                for (int np = 0; np < 4; np++) {
                    mma16816(c[mt][np * 2],     afh[mt], &bfh[np][0]);
                    mma16816(c[mt][np * 2 + 1], afh[mt], &bfh[np][2]);
                    mma16816(c[mt][np * 2],     afl[mt], &bfh[np][0]);
                    mma16816(c[mt][np * 2 + 1], afl[mt], &bfh[np][2]);
                    mma16816(c[mt][np * 2],     afh[mt], &bfl[np][0]);
                    mma16816(c[mt][np * 2 + 1], afh[mt], &bfl[np][2]);
                }
        }
        __syncthreads();
    }

    // ---------------- epilogue ----------------
    const int rbase = i0 + wr * 32 + (lane >> 2);
    const int cbase = j0 + wc * 64 + (lane & 3) * 2;
    if (MODE == 0) {
        #pragma unroll
        for (int mt = 0; mt < 2; mt++) {
            #pragma unroll
            for (int h2 = 0; h2 < 2; h2++) {
                int r = rbase + mt * 16 + h2 * 8;
                float* Erow = outb + SQ_OFF + (size_t)r * MM;
                #pragma unroll
                for (int nt = 0; nt < 8; nt++) {
                    int cc = cbase + nt * 8;
                    if (cc < MM) {
                        float2 e;
                        e.x = __expf(10.f * c[mt][nt][h2 * 2]);
                        e.y = __expf(10.f * c[mt][nt][h2 * 2 + 1]);
                        *(float2*)(Erow + cc) = e;
                    }
                }
            }
        }
    } else {
        #pragma unroll
        for (int mt = 0; mt < 2; mt++) {
            #pragma unroll
            for (int h2 = 0; h2 < 2; h2++) {
                int r = rbase + mt * 16 + h2 * 8;
                int bq = r >> 10, hw = r & 1023;
                float* base = outb + ((size_t)bq * 1024 + 512) * 1024 + hw;
                #pragma unroll
                for (int nt = 0; nt < 8; nt++) {
                    int cc = cbase + nt * 8;
                    base[(size_t)cc * 1024]       = c[mt][nt][h2 * 2];
                    base[(size_t)(cc + 1) * 1024] = c[mt][nt][h2 * 2 + 1];
                }
            }
        }
    }
}

// ---------------- K6a: column sum + max of E ---------------------------------
__global__ void k_colreduce(const float* __restrict__ outb) {
    const float* E = outb + SQ_OFF;
    int tx = threadIdx.x & 31, ty = threadIdx.x >> 5;   // grid (63,8)
    int m = blockIdx.x * 32 + tx;
    int n0 = blockIdx.y * 2048;
    float s = 0.f, mx = 0.f;
    if (m < MM) {
        const float* p = E + (size_t)n0 * MM + m;
        for (int r = ty; r < 2048; r += 8) { float v = p[(size_t)r * MM]; s += v; mx = fmaxf(mx, v); }
    }
    __shared__ float ss[8][33], sx[8][33];
    ss[ty][tx] = s; sx[ty][tx] = mx; __syncthreads();
    if (ty == 0 && m < MM) {
        for (int r = 1; r < 8; r++) { s += ss[r][tx]; mx = fmaxf(mx, sx[r][tx]); }
        atomicAdd(&g_colsum[m], s);
        atomicMax((int*)&g_colmaxE[m], __float_as_int(mx));   // E > 0
    }
}

__global__ void k_colinv() {
    int m = blockIdx.x * 256 + threadIdx.x;
    if (m < MM) g_colinv[m] = 1.0f / g_colsum[m];
}

// ---------------- K5: fused row pass ----------------------------------------
__global__ __launch_bounds__(256) void k_rows2(float* __restrict__ outb,
                                               const float* __restrict__ keys) {
    int n = blockIdx.x, tid = threadIdx.x;
    float* Er = outb + SQ_OFF  + (size_t)n * MM;
    float* Sr = outb + SMO_OFF + (size_t)n * MM;
    __shared__ float row[2048];
    __shared__ float rv1[256], rv2[256];
    __shared__ int   ri1[256], ri2[256];
    __shared__ float red[256];

    for (int m = tid; m < MM; m += 256) row[m] = Er[m];
    __syncthreads();

    float v1 = -3.0e38f, v2 = -3.0e38f; int i1 = 0x7FFFFFFF, i2 = 0x7FFFFFFF;
    for (int m = tid; m < MM; m += 256) {
        float v = row[m];
        if (gt2(v, m, v1, i1)) { v2 = v1; i2 = i1; v1 = v; i1 = m; }
        else if (gt2(v, m, v2, i2)) { v2 = v; i2 = m; }
    }
    rv1[tid] = v1; ri1[tid] = i1; rv2[tid] = v2; ri2[tid] = i2;
    __syncthreads();
    for (int s = 128; s > 0; s >>= 1) {
        if (tid < s) {
            float a1 = rv1[tid], a2 = rv2[tid]; int b1 = ri1[tid], b2 = ri2[tid];
            float w1 = rv1[tid + s], w2 = rv2[tid + s]; int j1 = ri1[tid + s], j2 = ri2[tid + s];
            float o1, o2; int p1, p2;
            if (gt2(a1, b1, w1, j1)) {
                o1 = a1; p1 = b1;
                if (gt2(w1, j1, a2, b2)) { o2 = w1; p2 = j1; } else { o2 = a2; p2 = b2; }
            } else {
                o1 = w1; p1 = j1;
                if (gt2(a1, b1, w2, j2)) { o2 = a1; p2 = b1; } else { o2 = w2; p2 = j2; }
            }
            rv1[tid] = o1; ri1[tid] = p1; rv2[tid] = o2; ri2[tid] = p2;
        }
        __syncthreads();
    }
    int gg1 = ri1[0], gg2 = ri2[0];

    float zs = 0.f;
    for (int m = tid; m < MM; m += 256) zs += row[m];
    zs = block_reduce_sum256(zs, red);
    float invZ = 1.0f / zs;

    __nv_bfloat16* smh = g_sm_h + (size_t)n * MP;
    __nv_bfloat16* sml = g_sm_l + (size_t)n * MP;
    for (int m = tid; m < MP; m += 256) {
        if (m < MM) {
            float e = row[m];
            float sm = e * invZ;
            Sr[m] = sm;                         // score_memory
            Er[m] = e * g_colinv[m];            // score_query (in place)
            __nv_bfloat16 h, lo; split2(sm, h, lo);
            smh[m] = h; sml[m] = lo;
        } else {
            __nv_bfloat16 z = __float2bfloat16(0.f);
            smh[m] = z; sml[m] = z;
        }
    }

    float c2 = 0.f, p2s = 0.f, n2s = 0.f;
    const float* qrow = g_qf + (size_t)n * 512;
    const float* k1 = keys + (size_t)gg1 * 512;
    const float* k2 = keys + (size_t)gg2 * 512;
    for (int d = tid; d < 512; d += 256) {
        float qv = qrow[d];
        float df = qv - k1[d];           c2 += df * df;
        float dp = df + 1e-6f;           p2s += dp * dp;
        float dn = (qv - k2[d]) + 1e-6f; n2s += dn * dn;
    }
    c2  = block_reduce_sum256(c2,  red);
    p2s = block_reduce_sum256(p2s, red);
    n2s = block_reduce_sum256(n2s, red);
    if (tid == 0) {
        atomicAdd(&g_loss[0], fmaxf(sqrtf(p2s) - sqrtf(n2s) + 1.0f, 0.0f));
        atomicAdd(&g_loss[1], c2);
        g_top1[n] = gg1;
        float ci = g_colinv[gg1];
        float wr = (rv1[0] * ci) / (g_colmaxE[gg1] * ci + 1e-8f);
        g_wraw[n] = wr;
        atomicAdd(&g_denom[gg1], wr);
    }
}

// ---------------- K7b: weighted segment scatter ------------------------------
__global__ void k_scatter() {
    int n = blockIdx.x;
    int g = g_top1[n];
    float w = g_wraw[n] / (g_denom[g] + 1e-8f);
    const float* qrow = g_qf + (size_t)n * 512;
    float* dst = g_qupd + (size_t)g * 512;
    for (int d = threadIdx.x; d < 512; d += 256) atomicAdd(&dst[d], w * qrow[d]);
}

// ---------------- K8: updated_memory -----------------------------------------
__global__ void k_umem(float* __restrict__ outb, const float* __restrict__ keys) {
    int m = blockIdx.x, tid = threadIdx.x;
    __shared__ float red[256];
    float a0 = g_qupd[(size_t)m * 512 + tid]       + keys[(size_t)m * 512 + tid];
    float a1 = g_qupd[(size_t)m * 512 + tid + 256] + keys[(size_t)m * 512 + tid + 256];
    float s = block_reduce_sum256(a0 * a0 + a1 * a1, red);
    float inv = 1.0f / fmaxf(sqrtf(s), 1e-12f);
    float* um = outb + UM_OFF + (size_t)m * 512;
    um[tid] = a0 * inv; um[tid + 256] = a1 * inv;
}

// ---------------- K9: finalize ------------------------------------------------
__global__ void k_final(float* __restrict__ outb) {
    outb[LS_OFF]     = g_loss[0] * (1.0f / 16384.0f);
    outb[LS_OFF + 1] = g_loss[1] * (1.0f / 8388608.0f);
}

// ---------------- launch ------------------------------------------------------
extern "C" void kernel_launch(void* const* d_in, const int* in_sizes, int n_in,
                              void* d_out, int out_size) {
    const float* q    = (const float*)d_in[0];
    const float* keys = (const float*)d_in[1];
    float* out = (float*)d_out;

    cudaFuncSetAttribute(k_mma<512, 0>,  cudaFuncAttributeMaxDynamicSharedMemorySize, HSM);
    cudaFuncSetAttribute(k_mma<2048, 1>, cudaFuncAttributeMaxDynamicSharedMemorySize, HSM);

    k_zero<<<4000, 256>>>();
    k_qnorm<<<dim3(64, 4), 256>>>(q);
    k_writeqf<<<dim3(16, 32, 16), dim3(32, 8)>>>(q, out);
    k_keynorm<<<2000, 256>>>(keys);
    k_keyT<<<dim3(64, 16), dim3(32, 8)>>>(keys);
    k_mma<512, 0><<<dim3(128, 16), 256, HSM>>>(out);
    k_colreduce<<<dim3(63, 8), 256>>>(out);
    k_colinv<<<8, 256>>>();
    k_rows2<<<16384, 256>>>(out, keys);
    k_mma<2048, 1><<<dim3(128, 4), 256, HSM>>>(out);
    k_scatter<<<16384, 256>>>();
    k_umem<<<2000, 256>>>(out, keys);
    k_final<<<1, 1>>>(out);
}

// round 8
// speedup vs baseline: 2.5514x; 1.1275x over previous
#include <cuda_runtime.h>
#include <cuda_bf16.h>
#include <math.h>
#include <stdint.h>

#define NN 16384
#define MM 2000
#define MP 2048

#define UQ_OFF 0LL
#define UM_OFF 16777216LL
#define SQ_OFF 17801216LL
#define SMO_OFF 50569216LL
#define LS_OFF 83337216LL
#define UQ_BSTRIDE 1048576LL

// ---------------- scratch ---------------------------------------------------
__device__ float g_qf[(size_t)NN*512];
__device__ __align__(16) __nv_bfloat16 g_qf_h[(size_t)NN*512], g_qf_l[(size_t)NN*512];
__device__ __align__(16) __nv_bfloat16 g_kn_h[(size_t)MP*512], g_kn_l[(size_t)MP*512];
__device__ __align__(16) __nv_bfloat16 g_kT_h[(size_t)512*MP], g_kT_l[(size_t)512*MP];
__device__ __align__(16) __nv_bfloat16 g_sm_h[(size_t)NN*MP],  g_sm_l[(size_t)NN*MP];
__device__ float g_colsum[MM], g_colmaxE[MM], g_colinv[MM];
__device__ float g_wraw[NN];
__device__ int   g_top1[NN];
__device__ float g_denom[MM];
__device__ float g_qupd[(size_t)MM*512];
__device__ float g_loss[2];

// ---------------- helpers ---------------------------------------------------
__device__ __forceinline__ bool gt2(float va, int ia, float vb, int ib) {
    return va > vb || (va == vb && (unsigned)ia < (unsigned)ib);
}
__device__ __forceinline__ float block_reduce_sum256(float v, float* red) {
    int tid = threadIdx.x;
    red[tid] = v; __syncthreads();
    #pragma unroll
    for (int s = 128; s > 0; s >>= 1) { if (tid < s) red[tid] += red[tid + s]; __syncthreads(); }
    float r = red[0]; __syncthreads(); return r;
}
__device__ __forceinline__ void split2(float v, __nv_bfloat16& h, __nv_bfloat16& l) {
    h = __float2bfloat16(v);
    l = __float2bfloat16(v - __bfloat162float(h));
}
__device__ __forceinline__ uint32_t s2u(const void* p) {
    uint32_t a;
    asm("{ .reg .u64 t; cvta.to.shared.u64 t, %1; cvt.u32.u64 %0, t; }" : "=r"(a) : "l"(p));
    return a;
}
__device__ __forceinline__ void ldm_x4(uint32_t* r, uint32_t addr) {
    asm volatile("ldmatrix.sync.aligned.m8n8.x4.shared.b16 {%0,%1,%2,%3}, [%4];"
        : "=r"(r[0]), "=r"(r[1]), "=r"(r[2]), "=r"(r[3]) : "r"(addr));
}
__device__ __forceinline__ void mma16816(float* c, const uint32_t* a, const uint32_t* b) {
    asm volatile("mma.sync.aligned.m16n8k16.row.col.f32.bf16.bf16.f32 "
        "{%0,%1,%2,%3}, {%4,%5,%6,%7}, {%8,%9}, {%0,%1,%2,%3};"
        : "+f"(c[0]), "+f"(c[1]), "+f"(c[2]), "+f"(c[3])
        : "r"(a[0]), "r"(a[1]), "r"(a[2]), "r"(a[3]), "r"(b[0]), "r"(b[1]));
}
#define CPA(dst, src) asm volatile("cp.async.cg.shared.global [%0], [%1], 16;" :: "r"(dst), "l"(src))
#define CPC()  asm volatile("cp.async.commit_group;" ::: "memory")

// ---------------- K0: zero scratch ------------------------------------------
__global__ void k_zero() {
    int i = blockIdx.x * 256 + threadIdx.x;       // 4000*256
    if (i < MM * 512) g_qupd[i] = 0.f;
    if (i < MM) { g_denom[i] = 0.f; g_colsum[i] = 0.f; g_colmaxE[i] = 0.f; }
    if (i < 2)  g_loss[i] = 0.f;
    if (i < 48 * 512) {                           // zero padded key rows
        __nv_bfloat16 z = __float2bfloat16(0.f);
        g_kn_h[(size_t)MM * 512 + i] = z;
        g_kn_l[(size_t)MM * 512 + i] = z;
    }
}

// ---------------- K1: fused query prep (norm + transpose + split + UQ) -------
// grid (32 hw-tiles, 16 b), 256 threads, dyn smem 32x521 floats.
__global__ __launch_bounds__(256) void k_prep(const float* __restrict__ q,
                                              float* __restrict__ outb) {
    extern __shared__ float sm[];                 // [32][521]
    __shared__ float inv_s[32];
    int hw0 = blockIdx.x * 32, b = blockIdx.y;
    int tid = threadIdx.x, lane = tid & 31, w = tid >> 5;
    const float* qb = q + (size_t)b * 524288;

    // load 512 x 32 tile (coalesced): sm[hw][d]
    for (int d = w; d < 512; d += 8)
        sm[lane * 521 + d] = qb[(size_t)d * 1024 + hw0 + lane];
    __syncthreads();

    // norms: warp w handles rows 4w..4w+3
    #pragma unroll
    for (int rr = 0; rr < 4; rr++) {
        int r = w * 4 + rr;
        float s = 0.f;
        #pragma unroll
        for (int k = 0; k < 16; k++) { float v = sm[r * 521 + lane + 32 * k]; s += v * v; }
        #pragma unroll
        for (int off = 16; off > 0; off >>= 1) s += __shfl_xor_sync(~0u, s, off);
        if (lane == 0) inv_s[r] = 1.0f / fmaxf(sqrtf(s), 1e-12f);
    }
    __syncthreads();

    // updated_query first half (channel-major)
    float* uq = outb + (size_t)b * UQ_BSTRIDE;
    for (int d = w; d < 512; d += 8)
        uq[(size_t)d * 1024 + hw0 + lane] = sm[lane * 521 + d] * inv_s[lane];

    // qf rows (pixel-major) + bf16 split
    #pragma unroll
    for (int rr = 0; rr < 4; rr++) {
        int r = w * 4 + rr;
        float iv = inv_s[r];
        size_t nbase = (size_t)(b * 1024 + hw0 + r) * 512;
        #pragma unroll
        for (int k = 0; k < 16; k++) {
            int d = lane + 32 * k;
            float v = sm[r * 521 + d] * iv;
            __nv_bfloat16 h, lo; split2(v, h, lo);
            g_qf[nbase + d] = v; g_qf_h[nbase + d] = h; g_qf_l[nbase + d] = lo;
        }
    }
}

// ---------------- K2: normalized keys bf16 split -----------------------------
__global__ void k_keynorm(const float* __restrict__ keys) {
    int m = blockIdx.x, tid = threadIdx.x;
    __shared__ float red[256];
    const float* kp = keys + (size_t)m * 512;
    float v0 = kp[tid], v1 = kp[tid + 256];
    float s = block_reduce_sum256(v0 * v0 + v1 * v1, red);
    float inv = 1.0f / fmaxf(sqrtf(s), 1e-12f);
    __nv_bfloat16 h, lo;
    split2(v0 * inv, h, lo);
    g_kn_h[(size_t)m * 512 + tid] = h; g_kn_l[(size_t)m * 512 + tid] = lo;
    split2(v1 * inv, h, lo);
    g_kn_h[(size_t)m * 512 + tid + 256] = h; g_kn_l[(size_t)m * 512 + tid + 256] = lo;
}

// ---------------- K2b: raw keys^T (512 x 2048 padded) bf16 split -------------
__global__ void k_keyT(const float* __restrict__ keys) {
    int m0 = blockIdx.x * 32, d0 = blockIdx.y * 32;   // grid (64,16), block (32,8)
    int tx = threadIdx.x, ty = threadIdx.y;
    __shared__ float t[32][33];
    #pragma unroll
    for (int qq = 0; qq < 4; qq++) {
        int ml = ty + qq * 8, m = m0 + ml;
        t[ml][tx] = (m < MM) ? keys[(size_t)m * 512 + d0 + tx] : 0.f;
    }
    __syncthreads();
    #pragma unroll
    for (int qq = 0; qq < 4; qq++) {
        int dl = ty + qq * 8;
        float v = t[tx][dl];
        size_t idx = (size_t)(d0 + dl) * MP + m0 + tx;
        __nv_bfloat16 h, lo; split2(v, h, lo);
        g_kT_h[idx] = h; g_kT_l[idx] = lo;
    }
}

// ---------------- HMMA GEMM -------------------------------------------------
// MODE 0: E=exp(10*(qf@kn^T)) -> SQ region + col sum/max atomics  (3 products)
// MODE 1: SM@keysT -> updated_query 2nd half                      (2 products)
#define ROWB 80
#define MATB 10240

template<int KTOT, int MODE>
__global__ __launch_bounds__(256, 1) void k_mma(float* __restrict__ outb) {
    constexpr int NMATS = (MODE == 0) ? 4 : 3;
    constexpr int STGB  = NMATS * MATB;
    extern __shared__ char smc[];
    const uint32_t smb = s2u(smc);
    const int tid = threadIdx.x;
    const int lane = tid & 31, wid = tid >> 5;
    const int wr = wid & 3, wc = wid >> 2;
    const int i0 = blockIdx.x * 128, j0 = blockIdx.y * 128;

    const __nv_bfloat16* Ah = (MODE == 0) ? g_qf_h : g_sm_h;
    const __nv_bfloat16* Al = (MODE == 0) ? g_qf_l : g_sm_l;
    const __nv_bfloat16* Bh = (MODE == 0) ? g_kn_h : g_kT_h;
    const __nv_bfloat16* Bl = (MODE == 0) ? g_kn_l : g_kT_h;   // Bl unused in MODE 1
    const int lda = (MODE == 0) ? 512 : MP;
    const int ldb = (MODE == 0) ? 512 : MP;

    float c[2][8][4];
    #pragma unroll
    for (int a = 0; a < 2; a++)
        #pragma unroll
        for (int b = 0; b < 8; b++)
            #pragma unroll
            for (int d = 0; d < 4; d++) c[a][b][d] = 0.f;

    const int NS = KTOT / 32;

    // prologue stage 0
    {
        #pragma unroll
        for (int i = 0; i < NMATS * 2; i++) {
            int chunk = tid + 256 * i;
            int mat = chunk >> 9, row = (chunk >> 2) & 127, kc = chunk & 3;
            const __nv_bfloat16* p = (mat == 0) ? Ah : (mat == 1) ? Al : (mat == 2) ? Bh : Bl;
            int rb = (mat < 2) ? i0 : j0;
            int gl = (mat < 2) ? lda : ldb;
            CPA(smb + mat * MATB + row * ROWB + kc * 16, p + (size_t)(rb + row) * gl + kc * 8);
        }
        CPC();
    }

    for (int s = 0; s < NS; s++) {
        if (s + 1 < NS) {
            uint32_t dst0 = smb + ((s + 1) & 1) * STGB;
            size_t k0 = (size_t)(s + 1) * 32;
            #pragma unroll
            for (int i = 0; i < NMATS * 2; i++) {
                int chunk = tid + 256 * i;
                int mat = chunk >> 9, row = (chunk >> 2) & 127, kc = chunk & 3;
                const __nv_bfloat16* p = (mat == 0) ? Ah : (mat == 1) ? Al : (mat == 2) ? Bh : Bl;
                int rb = (mat < 2) ? i0 : j0;
                int gl = (mat < 2) ? lda : ldb;
                CPA(dst0 + mat * MATB + row * ROWB + kc * 16, p + (size_t)(rb + row) * gl + k0 + kc * 8);
            }
            CPC();
            asm volatile("cp.async.wait_group 1;" ::: "memory");
        } else {
            asm volatile("cp.async.wait_group 0;" ::: "memory");
        }
        __syncthreads();

        uint32_t sb = smb + (s & 1) * STGB;
        #pragma unroll
        for (int kh = 0; kh < 2; kh++) {
            const int k16 = kh * 16;
            uint32_t afh[2][4], afl[2][4], bfh[4][4], bfl[4][4];
            #pragma unroll
            for (int mt = 0; mt < 2; mt++) {
                uint32_t ad = sb + (uint32_t)(wr * 32 + mt * 16 + (lane & 15)) * ROWB
                            + (uint32_t)(k16 + ((lane >> 4) << 3)) * 2;
                ldm_x4(afh[mt], ad);
                ldm_x4(afl[mt], ad + MATB);
            }
            #pragma unroll
            for (int np = 0; np < 4; np++) {
                int n = wc * 64 + np * 16 + ((lane >> 4) << 3) + (lane & 7);
                int kk = k16 + (((lane >> 3) & 1) << 3);
                uint32_t bd = sb + 2 * MATB + (uint32_t)n * ROWB + (uint32_t)kk * 2;
                ldm_x4(bfh[np], bd);
                if (MODE == 0) ldm_x4(bfl[np], bd + MATB);
            }
            #pragma unroll
            for (int mt = 0; mt < 2; mt++)
                #pragma unroll
                for (int np = 0; np < 4; np++) {
                    mma16816(c[mt][np * 2],     afh[mt], &bfh[np][0]);
                    mma16816(c[mt][np * 2 + 1], afh[mt], &bfh[np][2]);
                    mma16816(c[mt][np * 2],     afl[mt], &bfh[np][0]);
                    mma16816(c[mt][np * 2 + 1], afl[mt], &bfh[np][2]);
                    if (MODE == 0) {
                        mma16816(c[mt][np * 2],     afh[mt], &bfl[np][0]);
                        mma16816(c[mt][np * 2 + 1], afh[mt], &bfl[np][2]);
                    }
                }
        }
        __syncthreads();
    }

    // ---------------- epilogue ----------------
    const int rbase = i0 + wr * 32 + (lane >> 2);
    const int cbase = j0 + wc * 64 + (lane & 3) * 2;
    if (MODE == 0) {
        float csum[8][2], cmax[8][2];
        #pragma unroll
        for (int nt = 0; nt < 8; nt++) { csum[nt][0] = csum[nt][1] = 0.f; cmax[nt][0] = cmax[nt][1] = 0.f; }
        #pragma unroll
        for (int mt = 0; mt < 2; mt++) {
            #pragma unroll
            for (int h2 = 0; h2 < 2; h2++) {
                int r = rbase + mt * 16 + h2 * 8;
                float* Erow = outb + SQ_OFF + (size_t)r * MM;
                #pragma unroll
                for (int nt = 0; nt < 8; nt++) {
                    int cc = cbase + nt * 8;
                    float2 e;
                    e.x = __expf(10.f * c[mt][nt][h2 * 2]);
                    e.y = __expf(10.f * c[mt][nt][h2 * 2 + 1]);
                    if (cc < MM) *(float2*)(Erow + cc) = e;
                    csum[nt][0] += e.x; csum[nt][1] += e.y;
                    cmax[nt][0] = fmaxf(cmax[nt][0], e.x);
                    cmax[nt][1] = fmaxf(cmax[nt][1], e.y);
                }
            }
        }
        // reduce across the 8 lanes sharing a column set (lane bits 2-4)
        #pragma unroll
        for (int off = 4; off < 32; off <<= 1) {
            #pragma unroll
            for (int nt = 0; nt < 8; nt++) {
                csum[nt][0] += __shfl_xor_sync(~0u, csum[nt][0], off);
                csum[nt][1] += __shfl_xor_sync(~0u, csum[nt][1], off);
                cmax[nt][0] = fmaxf(cmax[nt][0], __shfl_xor_sync(~0u, cmax[nt][0], off));
                cmax[nt][1] = fmaxf(cmax[nt][1], __shfl_xor_sync(~0u, cmax[nt][1], off));
            }
        }
        if ((lane >> 2) == 0) {
            #pragma unroll
            for (int nt = 0; nt < 8; nt++) {
                int col = cbase + nt * 8;
                if (col < MM) {
                    atomicAdd(&g_colsum[col], csum[nt][0]);
                    atomicMax((int*)&g_colmaxE[col], __float_as_int(cmax[nt][0]));
                    atomicAdd(&g_colsum[col + 1], csum[nt][1]);
                    atomicMax((int*)&g_colmaxE[col + 1], __float_as_int(cmax[nt][1]));
                }
            }
        }
    } else {
        #pragma unroll
        for (int mt = 0; mt < 2; mt++) {
            #pragma unroll
            for (int h2 = 0; h2 < 2; h2++) {
                int r = rbase + mt * 16 + h2 * 8;
                int bq = r >> 10, hw = r & 1023;
                float* base = outb + ((size_t)bq * 1024 + 512) * 1024 + hw;
                #pragma unroll
                for (int nt = 0; nt < 8; nt++) {
                    int cc = cbase + nt * 8;
                    base[(size_t)cc * 1024]       = c[mt][nt][h2 * 2];
                    base[(size_t)(cc + 1) * 1024] = c[mt][nt][h2 * 2 + 1];
                }
            }
        }
    }
}

__global__ void k_colinv() {
    int m = blockIdx.x * 256 + threadIdx.x;
    if (m < MM) g_colinv[m] = 1.0f / g_colsum[m];
}

// ---------------- K5: fused row pass ----------------------------------------
__global__ __launch_bounds__(256) void k_rows2(float* __restrict__ outb,
                                               const float* __restrict__ keys) {
    int n = blockIdx.x, tid = threadIdx.x;
    float* Er = outb + SQ_OFF  + (size_t)n * MM;
    float* Sr = outb + SMO_OFF + (size_t)n * MM;
    __shared__ float row[2048];
    __shared__ float rv1[256], rv2[256];
    __shared__ int   ri1[256], ri2[256];
    __shared__ float red[256];

    for (int m = tid; m < MM; m += 256) row[m] = Er[m];
    __syncthreads();

    float v1 = -3.0e38f, v2 = -3.0e38f; int i1 = 0x7FFFFFFF, i2 = 0x7FFFFFFF;
    for (int m = tid; m < MM; m += 256) {
        float v = row[m];
        if (gt2(v, m, v1, i1)) { v2 = v1; i2 = i1; v1 = v; i1 = m; }
        else if (gt2(v, m, v2, i2)) { v2 = v; i2 = m; }
    }
    rv1[tid] = v1; ri1[tid] = i1; rv2[tid] = v2; ri2[tid] = i2;
    __syncthreads();
    for (int s = 128; s > 0; s >>= 1) {
        if (tid < s) {
            float a1 = rv1[tid], a2 = rv2[tid]; int b1 = ri1[tid], b2 = ri2[tid];
            float w1 = rv1[tid + s], w2 = rv2[tid + s]; int j1 = ri1[tid + s], j2 = ri2[tid + s];
            float o1, o2; int p1, p2;
            if (gt2(a1, b1, w1, j1)) {
                o1 = a1; p1 = b1;
                if (gt2(w1, j1, a2, b2)) { o2 = w1; p2 = j1; } else { o2 = a2; p2 = b2; }
            } else {
                o1 = w1; p1 = j1;
                if (gt2(a1, b1, w2, j2)) { o2 = a1; p2 = b1; } else { o2 = w2; p2 = j2; }
            }
            rv1[tid] = o1; ri1[tid] = p1; rv2[tid] = o2; ri2[tid] = p2;
        }
        __syncthreads();
    }
    int gg1 = ri1[0], gg2 = ri2[0];

    float zs = 0.f;
    for (int m = tid; m < MM; m += 256) zs += row[m];
    zs = block_reduce_sum256(zs, red);
    float invZ = 1.0f / zs;

    __nv_bfloat16* smh = g_sm_h + (size_t)n * MP;
    __nv_bfloat16* sml = g_sm_l + (size_t)n * MP;
    for (int m = tid; m < MP; m += 256) {
        if (m < MM) {
            float e = row[m];
            float sm = e * invZ;
            Sr[m] = sm;                         // score_memory
            Er[m] = e * g_colinv[m];            // score_query (in place)
            __nv_bfloat16 h, lo; split2(sm, h, lo);
            smh[m] = h; sml[m] = lo;
        } else {
            __nv_bfloat16 z = __float2bfloat16(0.f);
            smh[m] = z; sml[m] = z;
        }
    }

    float c2 = 0.f, p2s = 0.f, n2s = 0.f;
    const float* qrow = g_qf + (size_t)n * 512;
    const float* k1 = keys + (size_t)gg1 * 512;
    const float* k2 = keys + (size_t)gg2 * 512;
    for (int d = tid; d < 512; d += 256) {
        float qv = qrow[d];
        float df = qv - k1[d];           c2 += df * df;
        float dp = df + 1e-6f;           p2s += dp * dp;
        float dn = (qv - k2[d]) + 1e-6f; n2s += dn * dn;
    }
    c2  = block_reduce_sum256(c2,  red);
    p2s = block_reduce_sum256(p2s, red);
    n2s = block_reduce_sum256(n2s, red);
    if (tid == 0) {
        atomicAdd(&g_loss[0], fmaxf(sqrtf(p2s) - sqrtf(n2s) + 1.0f, 0.0f));
        atomicAdd(&g_loss[1], c2);
        g_top1[n] = gg1;
        float ci = g_colinv[gg1];
        float wr = (rv1[0] * ci) / (g_colmaxE[gg1] * ci + 1e-8f);
        g_wraw[n] = wr;
        atomicAdd(&g_denom[gg1], wr);
    }
}

// ---------------- K7b: weighted segment scatter ------------------------------
__global__ void k_scatter() {
    int n = blockIdx.x;
    int g = g_top1[n];
    float w = g_wraw[n] / (g_denom[g] + 1e-8f);
    const float* qrow = g_qf + (size_t)n * 512;
    float* dst = g_qupd + (size_t)g * 512;
    for (int d = threadIdx.x; d < 512; d += 256) atomicAdd(&dst[d], w * qrow[d]);
}

// ---------------- K8: updated_memory -----------------------------------------
__global__ void k_umem(float* __restrict__ outb, const float* __restrict__ keys) {
    int m = blockIdx.x, tid = threadIdx.x;
    __shared__ float red[256];
    float a0 = g_qupd[(size_t)m * 512 + tid]       + keys[(size_t)m * 512 + tid];
    float a1 = g_qupd[(size_t)m * 512 + tid + 256] + keys[(size_t)m * 512 + tid + 256];
    float s = block_reduce_sum256(a0 * a0 + a1 * a1, red);
    float inv = 1.0f / fmaxf(sqrtf(s), 1e-12f);
    float* um = outb + UM_OFF + (size_t)m * 512;
    um[tid] = a0 * inv; um[tid + 256] = a1 * inv;
}

// ---------------- K9: finalize ------------------------------------------------
__global__ void k_final(float* __restrict__ outb) {
    outb[LS_OFF]     = g_loss[0] * (1.0f / 16384.0f);
    outb[LS_OFF + 1] = g_loss[1] * (1.0f / 8388608.0f);
}

// ---------------- launch ------------------------------------------------------
extern "C" void kernel_launch(void* const* d_in, const int* in_sizes, int n_in,
                              void* d_out, int out_size) {
    const float* q    = (const float*)d_in[0];
    const float* keys = (const float*)d_in[1];
    float* out = (float*)d_out;

    const int PREP_SM = 32 * 521 * 4;       // 66688
    const int SM0 = 2 * 4 * MATB;           // 81920
    const int SM1 = 2 * 3 * MATB;           // 61440
    cudaFuncSetAttribute(k_prep,         cudaFuncAttributeMaxDynamicSharedMemorySize, PREP_SM);
    cudaFuncSetAttribute(k_mma<512, 0>,  cudaFuncAttributeMaxDynamicSharedMemorySize, SM0);
    cudaFuncSetAttribute(k_mma<2048, 1>, cudaFuncAttributeMaxDynamicSharedMemorySize, SM1);

    k_zero<<<4000, 256>>>();
    k_prep<<<dim3(32, 16), 256, PREP_SM>>>(q, out);
    k_keynorm<<<2000, 256>>>(keys);
    k_keyT<<<dim3(64, 16), dim3(32, 8)>>>(keys);
    k_mma<512, 0><<<dim3(128, 16), 256, SM0>>>(out);
    k_colinv<<<8, 256>>>();
    k_rows2<<<16384, 256>>>(out, keys);
    k_mma<2048, 1><<<dim3(128, 4), 256, SM1>>>(out);
    k_scatter<<<16384, 256>>>();
    k_umem<<<2000, 256>>>(out, keys);
    k_final<<<1, 1>>>(out);
}

// round 9
// speedup vs baseline: 5.1931x; 2.0354x over previous
#include <cuda_runtime.h>
#include <cuda_bf16.h>
#include <math.h>
#include <stdint.h>

#define NN 16384
#define MM 2000
#define MP 2048

#define UQ_OFF 0LL
#define UM_OFF 16777216LL
#define SQ_OFF 17801216LL
#define SMO_OFF 50569216LL
#define LS_OFF 83337216LL
#define UQ_BSTRIDE 1048576LL

// ---------------- scratch ---------------------------------------------------
__device__ float g_qf[(size_t)NN*512];
__device__ __align__(16) __nv_bfloat16 g_qf_h[(size_t)NN*512], g_qf_l[(size_t)NN*512];
__device__ __align__(16) __nv_bfloat16 g_kn_h[(size_t)MP*512], g_kn_l[(size_t)MP*512];
__device__ __align__(16) __nv_bfloat16 g_kT_h[(size_t)512*MP];
__device__ __align__(16) __nv_bfloat16 g_sm_h[(size_t)NN*MP];
__device__ float g_colsum[MM], g_colmaxE[MM], g_colinv[MM];
__device__ float g_wraw[NN];
__device__ int   g_top1[NN];
__device__ float g_denom[MM];
__device__ float g_qupd[(size_t)MM*512];
__device__ float g_loss[2];

// ---------------- helpers ---------------------------------------------------
__device__ __forceinline__ bool gt2(float va, int ia, float vb, int ib) {
    return va > vb || (va == vb && (unsigned)ia < (unsigned)ib);
}
__device__ __forceinline__ float block_reduce_sum256(float v, float* red) {
    int tid = threadIdx.x;
    red[tid] = v; __syncthreads();
    #pragma unroll
    for (int s = 128; s > 0; s >>= 1) { if (tid < s) red[tid] += red[tid + s]; __syncthreads(); }
    float r = red[0]; __syncthreads(); return r;
}
__device__ __forceinline__ void split2(float v, __nv_bfloat16& h, __nv_bfloat16& l) {
    h = __float2bfloat16(v);
    l = __float2bfloat16(v - __bfloat162float(h));
}
__device__ __forceinline__ uint32_t s2u(const void* p) {
    uint32_t a;
    asm("{ .reg .u64 t; cvta.to.shared.u64 t, %1; cvt.u32.u64 %0, t; }" : "=r"(a) : "l"(p));
    return a;
}
__device__ __forceinline__ void ldm_x4(uint32_t* r, uint32_t addr) {
    asm volatile("ldmatrix.sync.aligned.m8n8.x4.shared.b16 {%0,%1,%2,%3}, [%4];"
        : "=r"(r[0]), "=r"(r[1]), "=r"(r[2]), "=r"(r[3]) : "r"(addr));
}
__device__ __forceinline__ void mma16816(float* c, const uint32_t* a, const uint32_t* b) {
    asm volatile("mma.sync.aligned.m16n8k16.row.col.f32.bf16.bf16.f32 "
        "{%0,%1,%2,%3}, {%4,%5,%6,%7}, {%8,%9}, {%0,%1,%2,%3};"
        : "+f"(c[0]), "+f"(c[1]), "+f"(c[2]), "+f"(c[3])
        : "r"(a[0]), "r"(a[1]), "r"(a[2]), "r"(a[3]), "r"(b[0]), "r"(b[1]));
}
#define CPA(dst, src) asm volatile("cp.async.cg.shared.global [%0], [%1], 16;" :: "r"(dst), "l"(src))
#define CPC()  asm volatile("cp.async.commit_group;" ::: "memory")

// ---------------- K0: zero scratch ------------------------------------------
__global__ void k_zero() {
    int i = blockIdx.x * 256 + threadIdx.x;       // 4000*256
    if (i < MM * 512) g_qupd[i] = 0.f;
    if (i < MM) { g_denom[i] = 0.f; g_colsum[i] = 0.f; g_colmaxE[i] = 0.f; }
    if (i < 2)  g_loss[i] = 0.f;
    if (i < 48 * 512) {                           // zero padded key rows
        __nv_bfloat16 z = __float2bfloat16(0.f);
        g_kn_h[(size_t)MM * 512 + i] = z;
        g_kn_l[(size_t)MM * 512 + i] = z;
    }
}

// ---------------- K1: fused query prep (norm + transpose + split + UQ) -------
__global__ __launch_bounds__(256) void k_prep(const float* __restrict__ q,
                                              float* __restrict__ outb) {
    extern __shared__ float sm[];                 // [32][521]
    __shared__ float inv_s[32];
    int hw0 = blockIdx.x * 32, b = blockIdx.y;
    int tid = threadIdx.x, lane = tid & 31, w = tid >> 5;
    const float* qb = q + (size_t)b * 524288;

    for (int d = w; d < 512; d += 8)
        sm[lane * 521 + d] = qb[(size_t)d * 1024 + hw0 + lane];
    __syncthreads();

    #pragma unroll
    for (int rr = 0; rr < 4; rr++) {
        int r = w * 4 + rr;
        float s = 0.f;
        #pragma unroll
        for (int k = 0; k < 16; k++) { float v = sm[r * 521 + lane + 32 * k]; s += v * v; }
        #pragma unroll
        for (int off = 16; off > 0; off >>= 1) s += __shfl_xor_sync(~0u, s, off);
        if (lane == 0) inv_s[r] = 1.0f / fmaxf(sqrtf(s), 1e-12f);
    }
    __syncthreads();

    float* uq = outb + (size_t)b * UQ_BSTRIDE;
    for (int d = w; d < 512; d += 8)
        uq[(size_t)d * 1024 + hw0 + lane] = sm[lane * 521 + d] * inv_s[lane];

    #pragma unroll
    for (int rr = 0; rr < 4; rr++) {
        int r = w * 4 + rr;
        float iv = inv_s[r];
        size_t nbase = (size_t)(b * 1024 + hw0 + r) * 512;
        #pragma unroll
        for (int k = 0; k < 16; k++) {
            int d = lane + 32 * k;
            float v = sm[r * 521 + d] * iv;
            __nv_bfloat16 h, lo; split2(v, h, lo);
            g_qf[nbase + d] = v; g_qf_h[nbase + d] = h; g_qf_l[nbase + d] = lo;
        }
    }
}

// ---------------- K2: normalized keys bf16 split -----------------------------
__global__ void k_keynorm(const float* __restrict__ keys) {
    int m = blockIdx.x, tid = threadIdx.x;
    __shared__ float red[256];
    const float* kp = keys + (size_t)m * 512;
    float v0 = kp[tid], v1 = kp[tid + 256];
    float s = block_reduce_sum256(v0 * v0 + v1 * v1, red);
    float inv = 1.0f / fmaxf(sqrtf(s), 1e-12f);
    __nv_bfloat16 h, lo;
    split2(v0 * inv, h, lo);
    g_kn_h[(size_t)m * 512 + tid] = h; g_kn_l[(size_t)m * 512 + tid] = lo;
    split2(v1 * inv, h, lo);
    g_kn_h[(size_t)m * 512 + tid + 256] = h; g_kn_l[(size_t)m * 512 + tid + 256] = lo;
}

// ---------------- K2b: raw keys^T (512 x 2048 padded) bf16 hi ----------------
__global__ void k_keyT(const float* __restrict__ keys) {
    int m0 = blockIdx.x * 32, d0 = blockIdx.y * 32;   // grid (64,16), block (32,8)
    int tx = threadIdx.x, ty = threadIdx.y;
    __shared__ float t[32][33];
    #pragma unroll
    for (int qq = 0; qq < 4; qq++) {
        int ml = ty + qq * 8, m = m0 + ml;
        t[ml][tx] = (m < MM) ? keys[(size_t)m * 512 + d0 + tx] : 0.f;
    }
    __syncthreads();
    #pragma unroll
    for (int qq = 0; qq < 4; qq++) {
        int dl = ty + qq * 8;
        g_kT_h[(size_t)(d0 + dl) * MP + m0 + tx] = __float2bfloat16(t[tx][dl]);
    }
}

// ---------------- HMMA GEMM (warp tile 64x64, 4 warps) -----------------------
// MODE 0: E=exp(10*(qf@kn^T)) -> SQ region + col sum/max atomics  (3 products)
// MODE 1: SM@keysT -> updated_query 2nd half                      (1 product)
#define ROWB 80
#define MATB 10240

template<int KTOT, int MODE>
__global__ __launch_bounds__(128, 1) void k_mma(float* __restrict__ outb) {
    constexpr int NMATS = (MODE == 0) ? 4 : 2;
    constexpr int NA    = (MODE == 0) ? 2 : 1;   // A matrices before B in smem
    constexpr int STGB  = NMATS * MATB;
    constexpr int BOFF  = NA * MATB;
    extern __shared__ char smc[];
    const uint32_t smb = s2u(smc);
    const int tid = threadIdx.x;
    const int lane = tid & 31, wid = tid >> 5;
    const int wr = wid & 1, wc = wid >> 1;
    const int i0 = blockIdx.x * 128, j0 = blockIdx.y * 128;

    const __nv_bfloat16* Ah = (MODE == 0) ? g_qf_h : g_sm_h;
    const __nv_bfloat16* Al = (MODE == 0) ? g_qf_l : g_sm_h;   // unused in MODE 1
    const __nv_bfloat16* Bh = (MODE == 0) ? g_kn_h : g_kT_h;
    const __nv_bfloat16* Bl = (MODE == 0) ? g_kn_l : g_kT_h;   // unused in MODE 1
    const int lda = (MODE == 0) ? 512 : MP;
    const int ldb = (MODE == 0) ? 512 : MP;

    float c[4][8][4];
    #pragma unroll
    for (int a = 0; a < 4; a++)
        #pragma unroll
        for (int b = 0; b < 8; b++)
            #pragma unroll
            for (int d = 0; d < 4; d++) c[a][b][d] = 0.f;

    const int NS = KTOT / 32;
    constexpr int NITER = NMATS * 4;              // 16B chunks per thread per stage

    // prologue stage 0
    {
        #pragma unroll
        for (int i = 0; i < NITER; i++) {
            int chunk = tid + 128 * i;
            int mat = chunk >> 9, row = (chunk >> 2) & 127, kc = chunk & 3;
            const __nv_bfloat16* p = (mat == 0) ? Ah : (mat == 1) ? ((MODE == 0) ? Al : Bh)
                                   : (mat == 2) ? Bh : Bl;
            int rb = (mat < NA) ? i0 : j0;
            int gl = (mat < NA) ? lda : ldb;
            CPA(smb + mat * MATB + row * ROWB + kc * 16, p + (size_t)(rb + row) * gl + kc * 8);
        }
        CPC();
    }

    for (int s = 0; s < NS; s++) {
        if (s + 1 < NS) {
            uint32_t dst0 = smb + ((s + 1) & 1) * STGB;
            size_t k0 = (size_t)(s + 1) * 32;
            #pragma unroll
            for (int i = 0; i < NITER; i++) {
                int chunk = tid + 128 * i;
                int mat = chunk >> 9, row = (chunk >> 2) & 127, kc = chunk & 3;
                const __nv_bfloat16* p = (mat == 0) ? Ah : (mat == 1) ? ((MODE == 0) ? Al : Bh)
                                       : (mat == 2) ? Bh : Bl;
                int rb = (mat < NA) ? i0 : j0;
                int gl = (mat < NA) ? lda : ldb;
                CPA(dst0 + mat * MATB + row * ROWB + kc * 16, p + (size_t)(rb + row) * gl + k0 + kc * 8);
            }
            CPC();
            asm volatile("cp.async.wait_group 1;" ::: "memory");
        } else {
            asm volatile("cp.async.wait_group 0;" ::: "memory");
        }
        __syncthreads();

        uint32_t sb = smb + (s & 1) * STGB;
        #pragma unroll
        for (int kh = 0; kh < 2; kh++) {
            const int k16 = kh * 16;
            uint32_t afh[4][4], afl[4][4], bfh[4][4], bfl[4][4];
            #pragma unroll
            for (int mt = 0; mt < 4; mt++) {
                uint32_t ad = sb + (uint32_t)(wr * 64 + mt * 16 + (lane & 15)) * ROWB
                            + (uint32_t)(k16 + ((lane >> 4) << 3)) * 2;
                ldm_x4(afh[mt], ad);
                if (MODE == 0) ldm_x4(afl[mt], ad + MATB);
            }
            #pragma unroll
            for (int np = 0; np < 4; np++) {
                int n = wc * 64 + np * 16 + ((lane >> 4) << 3) + (lane & 7);
                int kk = k16 + (((lane >> 3) & 1) << 3);
                uint32_t bd = sb + BOFF + (uint32_t)n * ROWB + (uint32_t)kk * 2;
                ldm_x4(bfh[np], bd);
                if (MODE == 0) ldm_x4(bfl[np], bd + MATB);
            }
            #pragma unroll
            for (int mt = 0; mt < 4; mt++)
                #pragma unroll
                for (int np = 0; np < 4; np++) {
                    mma16816(c[mt][np * 2],     afh[mt], &bfh[np][0]);
                    mma16816(c[mt][np * 2 + 1], afh[mt], &bfh[np][2]);
                    if (MODE == 0) {
                        mma16816(c[mt][np * 2],     afl[mt], &bfh[np][0]);
                        mma16816(c[mt][np * 2 + 1], afl[mt], &bfh[np][2]);
                        mma16816(c[mt][np * 2],     afh[mt], &bfl[np][0]);
                        mma16816(c[mt][np * 2 + 1], afh[mt], &bfl[np][2]);
                    }
                }
        }
        __syncthreads();
    }

    // ---------------- epilogue ----------------
    const int rbase = i0 + wr * 64 + (lane >> 2);
    const int cbase = j0 + wc * 64 + (lane & 3) * 2;
    if (MODE == 0) {
        float csum[8][2], cmax[8][2];
        #pragma unroll
        for (int nt = 0; nt < 8; nt++) { csum[nt][0] = csum[nt][1] = 0.f; cmax[nt][0] = cmax[nt][1] = 0.f; }
        #pragma unroll
        for (int mt = 0; mt < 4; mt++) {
            #pragma unroll
            for (int h2 = 0; h2 < 2; h2++) {
                int r = rbase + mt * 16 + h2 * 8;
                float* Erow = outb + SQ_OFF + (size_t)r * MM;
                #pragma unroll
                for (int nt = 0; nt < 8; nt++) {
                    int cc = cbase + nt * 8;
                    float2 e;
                    e.x = __expf(10.f * c[mt][nt][h2 * 2]);
                    e.y = __expf(10.f * c[mt][nt][h2 * 2 + 1]);
                    if (cc < MM) *(float2*)(Erow + cc) = e;
                    csum[nt][0] += e.x; csum[nt][1] += e.y;
                    cmax[nt][0] = fmaxf(cmax[nt][0], e.x);
                    cmax[nt][1] = fmaxf(cmax[nt][1], e.y);
                }
            }
        }
        #pragma unroll
        for (int off = 4; off < 32; off <<= 1) {
            #pragma unroll
            for (int nt = 0; nt < 8; nt++) {
                csum[nt][0] += __shfl_xor_sync(~0u, csum[nt][0], off);
                csum[nt][1] += __shfl_xor_sync(~0u, csum[nt][1], off);
                cmax[nt][0] = fmaxf(cmax[nt][0], __shfl_xor_sync(~0u, cmax[nt][0], off));
                cmax[nt][1] = fmaxf(cmax[nt][1], __shfl_xor_sync(~0u, cmax[nt][1], off));
            }
        }
        if ((lane >> 2) == 0) {
            #pragma unroll
            for (int nt = 0; nt < 8; nt++) {
                int col = cbase + nt * 8;
                if (col < MM) {
                    atomicAdd(&g_colsum[col], csum[nt][0]);
                    atomicMax((int*)&g_colmaxE[col], __float_as_int(cmax[nt][0]));
                    atomicAdd(&g_colsum[col + 1], csum[nt][1]);
                    atomicMax((int*)&g_colmaxE[col + 1], __float_as_int(cmax[nt][1]));
                }
            }
        }
    } else {
        #pragma unroll
        for (int mt = 0; mt < 4; mt++) {
            #pragma unroll
            for (int h2 = 0; h2 < 2; h2++) {
                int r = rbase + mt * 16 + h2 * 8;
                int bq = r >> 10, hw = r & 1023;
                float* base = outb + ((size_t)bq * 1024 + 512) * 1024 + hw;
                #pragma unroll
                for (int nt = 0; nt < 8; nt++) {
                    int cc = cbase + nt * 8;
                    base[(size_t)cc * 1024]       = c[mt][nt][h2 * 2];
                    base[(size_t)(cc + 1) * 1024] = c[mt][nt][h2 * 2 + 1];
                }
            }
        }
    }
}

__global__ void k_colinv() {
    int m = blockIdx.x * 256 + threadIdx.x;
    if (m < MM) g_colinv[m] = 1.0f / g_colsum[m];
}

// ---------------- K5: fused row pass ----------------------------------------
__global__ __launch_bounds__(256) void k_rows2(float* __restrict__ outb,
                                               const float* __restrict__ keys) {
    int n = blockIdx.x, tid = threadIdx.x;
    float* Er = outb + SQ_OFF  + (size_t)n * MM;
    float* Sr = outb + SMO_OFF + (size_t)n * MM;
    __shared__ float row[2048];
    __shared__ float rv1[256], rv2[256];
    __shared__ int   ri1[256], ri2[256];
    __shared__ float red[256];

    for (int m = tid; m < MM; m += 256) row[m] = Er[m];
    __syncthreads();

    float v1 = -3.0e38f, v2 = -3.0e38f; int i1 = 0x7FFFFFFF, i2 = 0x7FFFFFFF;
    for (int m = tid; m < MM; m += 256) {
        float v = row[m];
        if (gt2(v, m, v1, i1)) { v2 = v1; i2 = i1; v1 = v; i1 = m; }
        else if (gt2(v, m, v2, i2)) { v2 = v; i2 = m; }
    }
    rv1[tid] = v1; ri1[tid] = i1; rv2[tid] = v2; ri2[tid] = i2;
    __syncthreads();
    for (int s = 128; s > 0; s >>= 1) {
        if (tid < s) {
            float a1 = rv1[tid], a2 = rv2[tid]; int b1 = ri1[tid], b2 = ri2[tid];
            float w1 = rv1[tid + s], w2 = rv2[tid + s]; int j1 = ri1[tid + s], j2 = ri2[tid + s];
            float o1, o2; int p1, p2;
            if (gt2(a1, b1, w1, j1)) {
                o1 = a1; p1 = b1;
                if (gt2(w1, j1, a2, b2)) { o2 = w1; p2 = j1; } else { o2 = a2; p2 = b2; }
            } else {
                o1 = w1; p1 = j1;
                if (gt2(a1, b1, w2, j2)) { o2 = a1; p2 = b1; } else { o2 = w2; p2 = j2; }
            }
            rv1[tid] = o1; ri1[tid] = p1; rv2[tid] = o2; ri2[tid] = p2;
        }
        __syncthreads();
    }
    int gg1 = ri1[0], gg2 = ri2[0];

    float zs = 0.f;
    for (int m = tid; m < MM; m += 256) zs += row[m];
    zs = block_reduce_sum256(zs, red);
    float invZ = 1.0f / zs;

    __nv_bfloat16* smh = g_sm_h + (size_t)n * MP;
    for (int m = tid; m < MP; m += 256) {
        if (m < MM) {
            float e = row[m];
            float sm = e * invZ;
            Sr[m] = sm;                         // score_memory
            Er[m] = e * g_colinv[m];            // score_query (in place)
            smh[m] = __float2bfloat16(sm);
        } else {
            smh[m] = __float2bfloat16(0.f);
        }
    }

    float c2 = 0.f, p2s = 0.f, n2s = 0.f;
    const float* qrow = g_qf + (size_t)n * 512;
    const float* k1 = keys + (size_t)gg1 * 512;
    const float* k2 = keys + (size_t)gg2 * 512;
    for (int d = tid; d < 512; d += 256) {
        float qv = qrow[d];
        float df = qv - k1[d];           c2 += df * df;
        float dp = df + 1e-6f;           p2s += dp * dp;
        float dn = (qv - k2[d]) + 1e-6f; n2s += dn * dn;
    }
    c2  = block_reduce_sum256(c2,  red);
    p2s = block_reduce_sum256(p2s, red);
    n2s = block_reduce_sum256(n2s, red);
    if (tid == 0) {
        atomicAdd(&g_loss[0], fmaxf(sqrtf(p2s) - sqrtf(n2s) + 1.0f, 0.0f));
        atomicAdd(&g_loss[1], c2);
        g_top1[n] = gg1;
        float ci = g_colinv[gg1];
        float wr = (rv1[0] * ci) / (g_colmaxE[gg1] * ci + 1e-8f);
        g_wraw[n] = wr;
        atomicAdd(&g_denom[gg1], wr);
    }
}

// ---------------- K7b: weighted segment scatter ------------------------------
__global__ void k_scatter() {
    int n = blockIdx.x;
    int g = g_top1[n];
    float w = g_wraw[n] / (g_denom[g] + 1e-8f);
    const float* qrow = g_qf + (size_t)n * 512;
    float* dst = g_qupd + (size_t)g * 512;
    for (int d = threadIdx.x; d < 512; d += 256) atomicAdd(&dst[d], w * qrow[d]);
}

// ---------------- K8: updated_memory -----------------------------------------
__global__ void k_umem(float* __restrict__ outb, const float* __restrict__ keys) {
    int m = blockIdx.x, tid = threadIdx.x;
    __shared__ float red[256];
    float a0 = g_qupd[(size_t)m * 512 + tid]       + keys[(size_t)m * 512 + tid];
    float a1 = g_qupd[(size_t)m * 512 + tid + 256] + keys[(size_t)m * 512 + tid + 256];
    float s = block_reduce_sum256(a0 * a0 + a1 * a1, red);
    float inv = 1.0f / fmaxf(sqrtf(s), 1e-12f);
    float* um = outb + UM_OFF + (size_t)m * 512;
    um[tid] = a0 * inv; um[tid + 256] = a1 * inv;
}

// ---------------- K9: finalize ------------------------------------------------
__global__ void k_final(float* __restrict__ outb) {
    outb[LS_OFF]     = g_loss[0] * (1.0f / 16384.0f);
    outb[LS_OFF + 1] = g_loss[1] * (1.0f / 8388608.0f);
}

// ---------------- launch ------------------------------------------------------
extern "C" void kernel_launch(void* const* d_in, const int* in_sizes, int n_in,
                              void* d_out, int out_size) {
    const float* q    = (const float*)d_in[0];
    const float* keys = (const float*)d_in[1];
    float* out = (float*)d_out;

    const int PREP_SM = 32 * 521 * 4;       // 66688
    const int SM0 = 2 * 4 * MATB;           // 81920
    const int SM1 = 2 * 2 * MATB;           // 40960
    cudaFuncSetAttribute(k_prep,         cudaFuncAttributeMaxDynamicSharedMemorySize, PREP_SM);
    cudaFuncSetAttribute(k_mma<512, 0>,  cudaFuncAttributeMaxDynamicSharedMemorySize, SM0);
    cudaFuncSetAttribute(k_mma<2048, 1>, cudaFuncAttributeMaxDynamicSharedMemorySize, SM1);

    k_zero<<<4000, 256>>>();
    k_prep<<<dim3(32, 16), 256, PREP_SM>>>(q, out);
    k_keynorm<<<2000, 256>>>(keys);
    k_keyT<<<dim3(64, 16), dim3(32, 8)>>>(keys);
    k_mma<512, 0><<<dim3(128, 16), 128, SM0>>>(out);
    k_colinv<<<8, 256>>>();
    k_rows2<<<16384, 256>>>(out, keys);
    k_mma<2048, 1><<<dim3(128, 4), 128, SM1>>>(out);
    k_scatter<<<16384, 256>>>();
    k_umem<<<2000, 256>>>(out, keys);
    k_final<<<1, 1>>>(out);
}